// round 3
// baseline (speedup 1.0000x reference)
#include <cuda_runtime.h>
#include <math.h>

// Problem constants
#define DIMD   768
#define MROWS  8192          // B*N = 4*2048
#define NHEADS 16
#define HD     48
#define SEQ    2048
#define SQRT48 6.9282032302755091741f

// Scratch (sanctioned __device__ global workaround; no allocations anywhere)
__device__ float g_q[MROWS * DIMD];
__device__ float g_k[MROWS * DIMD];
__device__ float g_v[MROWS * DIMD];
__device__ float g_attn[MROWS * DIMD];

// ---------------------------------------------------------------------------
// SGEMM: C[M x 768] = A[M x 768] @ W[768 x 768]^T + bias
// BM=BN=128, BK=8, 256 threads, 8x8 per thread, smem padded to 132 for
// conflict-free transposed stores and float4 fragment loads.
// ---------------------------------------------------------------------------
__device__ __forceinline__ void gemm_body(const float* __restrict__ A,
                                          const float* __restrict__ W,
                                          const float* __restrict__ bias,
                                          float* __restrict__ C)
{
    __shared__ float As[8][132];
    __shared__ float Ws[8][132];

    const int tid = threadIdx.x;
    const int m0  = blockIdx.y * 128;
    const int n0  = blockIdx.x * 128;
    const int lr  = tid >> 1;          // 0..127 : row within tile
    const int lc  = (tid & 1) << 2;    // 0 or 4 : k-offset within BK
    const int tx  = tid & 15;          // output col group
    const int ty  = tid >> 4;          // output row group

    const float* Ap = A + (size_t)(m0 + lr) * DIMD + lc;
    const float* Wp = W + (size_t)(n0 + lr) * DIMD + lc;

    float4 pa = *(const float4*)Ap;
    float4 pw = *(const float4*)Wp;

    float acc[8][8];
#pragma unroll
    for (int i = 0; i < 8; i++)
#pragma unroll
        for (int j = 0; j < 8; j++) acc[i][j] = 0.f;

#pragma unroll 1
    for (int t = 0; t < DIMD / 8; ++t) {
        As[lc + 0][lr] = pa.x; As[lc + 1][lr] = pa.y;
        As[lc + 2][lr] = pa.z; As[lc + 3][lr] = pa.w;
        Ws[lc + 0][lr] = pw.x; Ws[lc + 1][lr] = pw.y;
        Ws[lc + 2][lr] = pw.z; Ws[lc + 3][lr] = pw.w;
        __syncthreads();

        if (t < DIMD / 8 - 1) {  // prefetch next k-tile into registers
            pa = *(const float4*)(Ap + (t + 1) * 8);
            pw = *(const float4*)(Wp + (t + 1) * 8);
        }

#pragma unroll
        for (int k = 0; k < 8; ++k) {
            float4 a0 = *(const float4*)&As[k][ty * 8];
            float4 a1 = *(const float4*)&As[k][ty * 8 + 4];
            float4 b0 = *(const float4*)&Ws[k][tx * 8];
            float4 b1 = *(const float4*)&Ws[k][tx * 8 + 4];
            float av[8] = {a0.x, a0.y, a0.z, a0.w, a1.x, a1.y, a1.z, a1.w};
            float bv[8] = {b0.x, b0.y, b0.z, b0.w, b1.x, b1.y, b1.z, b1.w};
#pragma unroll
            for (int i = 0; i < 8; i++)
#pragma unroll
                for (int j = 0; j < 8; j++)
                    acc[i][j] = fmaf(av[i], bv[j], acc[i][j]);
        }
        __syncthreads();
    }

    float bb[8];
#pragma unroll
    for (int j = 0; j < 8; j++) bb[j] = bias[n0 + tx * 8 + j];
#pragma unroll
    for (int i = 0; i < 8; i++) {
        float* crow = C + (size_t)(m0 + ty * 8 + i) * DIMD + n0 + tx * 8;
        float4 r0 = make_float4(acc[i][0] + bb[0], acc[i][1] + bb[1],
                                acc[i][2] + bb[2], acc[i][3] + bb[3]);
        float4 r1 = make_float4(acc[i][4] + bb[4], acc[i][5] + bb[5],
                                acc[i][6] + bb[6], acc[i][7] + bb[7]);
        *(float4*)crow       = r0;
        *(float4*)(crow + 4) = r1;
    }
}

__global__ void __launch_bounds__(256, 2)
qkv_kernel(const float* __restrict__ x,
           const float* __restrict__ Wq, const float* __restrict__ bq,
           const float* __restrict__ Wk, const float* __restrict__ bk,
           const float* __restrict__ Wv, const float* __restrict__ bv)
{
    const float* W; const float* b; float* C;
    if (blockIdx.z == 0)      { W = Wq; b = bq; C = g_q; }
    else if (blockIdx.z == 1) { W = Wk; b = bk; C = g_k; }
    else                      { W = Wv; b = bv; C = g_v; }
    gemm_body(x, W, b, C);
}

__global__ void __launch_bounds__(256, 2)
proj_kernel(const float* __restrict__ Wo, const float* __restrict__ bo,
            float* __restrict__ out)
{
    gemm_body(g_attn, Wo, bo, out);
}

// ---------------------------------------------------------------------------
// Attention: one block per (b,h, 128-row query tile). Raw-view layout means
// the (b,h) slab is just a contiguous 2048x48 chunk of g_q/g_k/g_v.
// S (128x128) in registers 8x8/thread; online softmax with 16-lane shfl
// reductions; P staged through padded smem; PV with 8x3 output frags.
// ---------------------------------------------------------------------------
#define SQS 128   // d-major stride for sQ/sK
#define SVS 52    // padded stride for sV rows
#define SPS 132   // padded stride for sP rows (float4-aligned)
#define ATTN_SMEM_FLOATS (48*SQS + 48*SQS + 128*SVS + 128*SPS)
#define ATTN_SMEM_BYTES  (ATTN_SMEM_FLOATS * 4)

__global__ void __launch_bounds__(256, 1)
attn_kernel()
{
    extern __shared__ float sm[];
    float* sQ = sm;                       // [48][128] d-major, pre-scaled by sqrt(48)
    float* sK = sQ + 48 * SQS;            // [48][128] d-major
    float* sV = sK + 48 * SQS;            // [128][52] row-major
    float* sP = sV + 128 * SVS;           // [128][132]

    const int tid  = threadIdx.x;
    const int tx   = tid & 15;            // S col group / PV col group
    const int ty   = tid >> 4;            // row group (shared by S and PV phases)
    const int bid  = blockIdx.x;
    const int qt   = bid & 15;
    const size_t slab = (size_t)(bid >> 4) * (SEQ * HD);  // (b,h) slab base
    const int q0   = qt * 128;
    const int cx3  = tx * 3;

    // ---- load Q tile (once), transposed to d-major, scaled by sqrt(48)
    {
        const int r  = tid & 127;
        const int hf = tid >> 7;          // 0/1 : which 24-dim half
        const float* src = g_q + slab + (size_t)(q0 + r) * HD + hf * 24;
#pragma unroll
        for (int u = 0; u < 6; u++) {
            float4 v = *(const float4*)(src + u * 4);
            int d0 = hf * 24 + u * 4;
            sQ[(d0 + 0) * SQS + r] = v.x * SQRT48;
            sQ[(d0 + 1) * SQS + r] = v.y * SQRT48;
            sQ[(d0 + 2) * SQS + r] = v.z * SQRT48;
            sQ[(d0 + 3) * SQS + r] = v.w * SQRT48;
        }
    }

    float o[8][3];
    float mrow[8], lrow[8];
#pragma unroll
    for (int i = 0; i < 8; i++) {
        mrow[i] = -INFINITY; lrow[i] = 0.f;
        o[i][0] = o[i][1] = o[i][2] = 0.f;
    }

    for (int t = 0; t < SEQ / 128; ++t) {
        __syncthreads();  // prev PV done reading sV/sP; Q store visible at t=0

        // ---- load K tile (transposed to d-major) and V tile (row-major)
        {
            const int r  = tid & 127;
            const int hf = tid >> 7;
            const float* src = g_k + slab + (size_t)(t * 128 + r) * HD + hf * 24;
#pragma unroll
            for (int u = 0; u < 6; u++) {
                float4 v = *(const float4*)(src + u * 4);
                int d0 = hf * 24 + u * 4;
                sK[(d0 + 0) * SQS + r] = v.x;
                sK[(d0 + 1) * SQS + r] = v.y;
                sK[(d0 + 2) * SQS + r] = v.z;
                sK[(d0 + 3) * SQS + r] = v.w;
            }
        }
        {
            const float* vbase = g_v + slab + (size_t)(t * 128) * HD;
#pragma unroll
            for (int u = 0; u < 6; u++) {
                int fi = tid + 256 * u;       // float4 index, 1536 total
                int rr = fi / 12;
                int dq = fi - rr * 12;
                float4 v = *(const float4*)(vbase + rr * HD + dq * 4);
                *(float4*)(sV + rr * SVS + dq * 4) = v;
            }
        }
        __syncthreads();

        // ---- S = (q*sqrt48) . k^T, 8x8 per thread
        float acc[8][8];
#pragma unroll
        for (int i = 0; i < 8; i++)
#pragma unroll
            for (int j = 0; j < 8; j++) acc[i][j] = 0.f;

#pragma unroll 4
        for (int d = 0; d < HD; ++d) {
            float4 a0 = *(const float4*)(sQ + d * SQS + ty * 8);
            float4 a1 = *(const float4*)(sQ + d * SQS + ty * 8 + 4);
            float4 b0 = *(const float4*)(sK + d * SQS + tx * 8);
            float4 b1 = *(const float4*)(sK + d * SQS + tx * 8 + 4);
            float av[8] = {a0.x, a0.y, a0.z, a0.w, a1.x, a1.y, a1.z, a1.w};
            float bv[8] = {b0.x, b0.y, b0.z, b0.w, b1.x, b1.y, b1.z, b1.w};
#pragma unroll
            for (int i = 0; i < 8; i++)
#pragma unroll
                for (int j = 0; j < 8; j++)
                    acc[i][j] = fmaf(av[i], bv[j], acc[i][j]);
        }

        // ---- online softmax (row stats across 16 tx lanes) + write P
#pragma unroll
        for (int i = 0; i < 8; i++) {
            float mt = acc[i][0];
#pragma unroll
            for (int j = 1; j < 8; j++) mt = fmaxf(mt, acc[i][j]);
            mt = fmaxf(mt, __shfl_xor_sync(0xffffffffu, mt, 1));
            mt = fmaxf(mt, __shfl_xor_sync(0xffffffffu, mt, 2));
            mt = fmaxf(mt, __shfl_xor_sync(0xffffffffu, mt, 4));
            mt = fmaxf(mt, __shfl_xor_sync(0xffffffffu, mt, 8));

            float mnew = fmaxf(mrow[i], mt);
            float fi   = __expf(mrow[i] - mnew);   // 0 on first tile
            mrow[i] = mnew;

            float rs = 0.f;
#pragma unroll
            for (int j = 0; j < 8; j++) {
                float p = __expf(acc[i][j] - mnew);
                acc[i][j] = p;
                rs += p;
            }
            rs += __shfl_xor_sync(0xffffffffu, rs, 1);
            rs += __shfl_xor_sync(0xffffffffu, rs, 2);
            rs += __shfl_xor_sync(0xffffffffu, rs, 4);
            rs += __shfl_xor_sync(0xffffffffu, rs, 8);

            lrow[i] = lrow[i] * fi + rs;
            o[i][0] *= fi; o[i][1] *= fi; o[i][2] *= fi;

            *(float4*)(sP + (ty * 8 + i) * SPS + tx * 8) =
                make_float4(acc[i][0], acc[i][1], acc[i][2], acc[i][3]);
            *(float4*)(sP + (ty * 8 + i) * SPS + tx * 8 + 4) =
                make_float4(acc[i][4], acc[i][5], acc[i][6], acc[i][7]);
        }
        __syncthreads();

        // ---- O += P @ V   (8 rows x 3 cols per thread)
        const float* prow = sP + (size_t)(ty * 8) * SPS;
#pragma unroll 2
        for (int j = 0; j < 128; ++j) {
            float v0 = sV[j * SVS + cx3 + 0];
            float v1 = sV[j * SVS + cx3 + 1];
            float v2 = sV[j * SVS + cx3 + 2];
#pragma unroll
            for (int i = 0; i < 8; i++) {
                float p = prow[i * SPS + j];
                o[i][0] = fmaf(p, v0, o[i][0]);
                o[i][1] = fmaf(p, v1, o[i][1]);
                o[i][2] = fmaf(p, v2, o[i][2]);
            }
        }
    }

    // ---- finalize: divide by l, write to g_attn (raw-view layout)
#pragma unroll
    for (int i = 0; i < 8; i++) {
        float inv = 1.f / lrow[i];
        float* dst = g_attn + slab + (size_t)(q0 + ty * 8 + i) * HD + cx3;
        dst[0] = o[i][0] * inv;
        dst[1] = o[i][1] * inv;
        dst[2] = o[i][2] * inv;
    }
}

// ---------------------------------------------------------------------------
extern "C" void kernel_launch(void* const* d_in, const int* in_sizes, int n_in,
                              void* d_out, int out_size)
{
    const float* x  = (const float*)d_in[0];
    const float* Wq = (const float*)d_in[1];
    const float* bq = (const float*)d_in[2];
    const float* Wk = (const float*)d_in[3];
    const float* bk = (const float*)d_in[4];
    const float* Wv = (const float*)d_in[5];
    const float* bv = (const float*)d_in[6];
    const float* Wo = (const float*)d_in[7];
    const float* bo = (const float*)d_in[8];
    float* out = (float*)d_out;

    // Idempotent, host-side, capture-safe
    cudaFuncSetAttribute(attn_kernel,
                         cudaFuncAttributeMaxDynamicSharedMemorySize,
                         ATTN_SMEM_BYTES);

    dim3 gqkv(DIMD / 128, MROWS / 128, 3);   // 6 x 64 x 3
    qkv_kernel<<<gqkv, 256>>>(x, Wq, bq, Wk, bk, Wv, bv);

    attn_kernel<<<(MROWS / 128) * NHEADS, 256, ATTN_SMEM_BYTES>>>();  // 1024 blocks

    dim3 gproj(DIMD / 128, MROWS / 128);     // 6 x 64
    proj_kernel<<<gproj, 256>>>(Wo, bo, out);

    (void)in_sizes; (void)n_in; (void)out_size;
}

// round 5
// speedup vs baseline: 1.1974x; 1.1974x over previous
#include <cuda_runtime.h>
#include <cuda_bf16.h>
#include <math.h>
#include <stdint.h>

// Problem constants
#define DIMD   768
#define MROWS  8192          // B*N = 4*2048
#define NHEADS 16
#define HD     48
#define SEQ    2048
#define SQRT48 6.9282032302755091741f
#define WELEMS (DIMD * DIMD)

// ---------------------------------------------------------------------------
// Scratch (__device__ globals; no allocations anywhere)
// ---------------------------------------------------------------------------
__device__ float g_q[MROWS * DIMD];
__device__ float g_k[MROWS * DIMD];
__device__ float g_v[MROWS * DIMD];
__device__ __nv_bfloat16 g_xhi[MROWS * DIMD];
__device__ __nv_bfloat16 g_xlo[MROWS * DIMD];
__device__ __nv_bfloat16 g_ahi[MROWS * DIMD];
__device__ __nv_bfloat16 g_alo[MROWS * DIMD];
__device__ __nv_bfloat16 g_whi[4 * WELEMS];
__device__ __nv_bfloat16 g_wlo[4 * WELEMS];

// ---------------------------------------------------------------------------
// mma.sync helpers (baseline PTX — legal on plain sm_100 target)
// ---------------------------------------------------------------------------
__device__ __forceinline__ uint32_t smem_u32(const void* p) {
    uint32_t a;
    asm("{ .reg .u64 t; cvta.to.shared.u64 t, %1; cvt.u32.u64 %0, t; }"
        : "=r"(a) : "l"(p));
    return a;
}

__device__ __forceinline__ void ldm_x4(uint32_t* r, uint32_t addr) {
    asm volatile("ldmatrix.sync.aligned.m8n8.x4.shared.b16 {%0,%1,%2,%3}, [%4];"
                 : "=r"(r[0]), "=r"(r[1]), "=r"(r[2]), "=r"(r[3]) : "r"(addr));
}

__device__ __forceinline__ void mma16816(float* c, const uint32_t* a,
                                         const uint32_t* b) {
    asm volatile(
        "mma.sync.aligned.m16n8k16.row.col.f32.bf16.bf16.f32 "
        "{%0,%1,%2,%3}, {%4,%5,%6,%7}, {%8,%9}, {%0,%1,%2,%3};"
        : "+f"(c[0]), "+f"(c[1]), "+f"(c[2]), "+f"(c[3])
        : "r"(a[0]), "r"(a[1]), "r"(a[2]), "r"(a[3]), "r"(b[0]), "r"(b[1]));
}

// ---------------------------------------------------------------------------
// Conversion kernels: f32 -> (hi, lo) bf16 pair
// ---------------------------------------------------------------------------
__device__ __forceinline__ void split1(float v, __nv_bfloat16* hi, __nv_bfloat16* lo) {
    __nv_bfloat16 h = __float2bfloat16(v);
    *hi = h;
    *lo = __float2bfloat16(v - __bfloat162float(h));
}

__global__ void convert_x_kernel(const float* __restrict__ x) {
    int i4 = blockIdx.x * 256 + threadIdx.x;
    float4 v = ((const float4*)x)[i4];
    size_t b = (size_t)i4 * 4;
    split1(v.x, &g_xhi[b + 0], &g_xlo[b + 0]);
    split1(v.y, &g_xhi[b + 1], &g_xlo[b + 1]);
    split1(v.z, &g_xhi[b + 2], &g_xlo[b + 2]);
    split1(v.w, &g_xhi[b + 3], &g_xlo[b + 3]);
}

__global__ void convert_w_kernel(const float* __restrict__ Wq,
                                 const float* __restrict__ Wk,
                                 const float* __restrict__ Wv,
                                 const float* __restrict__ Wo) {
    int i4 = blockIdx.x * 256 + threadIdx.x;
    int per = WELEMS / 4;
    int mat = i4 / per;
    int off = i4 - mat * per;
    const float* src = (mat == 0) ? Wq : (mat == 1) ? Wk : (mat == 2) ? Wv : Wo;
    float4 v = ((const float4*)src)[off];
    size_t b = (size_t)mat * WELEMS + (size_t)off * 4;
    split1(v.x, &g_whi[b + 0], &g_wlo[b + 0]);
    split1(v.y, &g_whi[b + 1], &g_wlo[b + 1]);
    split1(v.z, &g_whi[b + 2], &g_wlo[b + 2]);
    split1(v.w, &g_whi[b + 3], &g_wlo[b + 3]);
}

// ---------------------------------------------------------------------------
// Tensor-core split-bf16 GEMM via mma.sync:
//   C[128x128 tile] = A @ W^T + bias, A/W pre-split hi/lo bf16, K-major.
// 256 threads = 8 warps (2 m x 4 n), warp tile 64x32.
// SMEM: 4 tiles of 128 rows x 128B (SW128 swizzle), BK=64 per chunk.
// Per frag-pair: 3 mma (hi*hi, hi*lo, lo*hi) -> fp32 accum.
// ---------------------------------------------------------------------------
#define GEMM_SMEM_BYTES (4 * 16384)

__device__ __forceinline__ void gemm_tc_body(const __nv_bfloat16* __restrict__ Ahi,
                                             const __nv_bfloat16* __restrict__ Alo,
                                             const __nv_bfloat16* __restrict__ Whi,
                                             const __nv_bfloat16* __restrict__ Wlo,
                                             const float* __restrict__ bias,
                                             float* __restrict__ C)
{
    extern __shared__ char smem[];
    char* sAhi = smem;
    char* sAlo = smem + 16384;
    char* sWhi = smem + 32768;
    char* sWlo = smem + 49152;

    const int tid  = threadIdx.x;
    const int wid  = tid >> 5;
    const int lane = tid & 31;
    const int m0 = blockIdx.y * 128;
    const int n0 = blockIdx.x * 128;
    const int wm = wid >> 2;           // 0..1
    const int wn = wid & 3;            // 0..3
    const int mBase = wm * 64;
    const int nBase = wn * 32;

    // ldmatrix address components (swizzle: col ^ ((row&7)*16), rows are 128B)
    const uint32_t xork = (lane & 7) * 16;
    const uint32_t aRow = smem_u32(sAhi) + (uint32_t)(mBase + (lane & 15)) * 128;
    const uint32_t aCol = ((lane >> 4) & 1) * 16;
    const uint32_t bRow = smem_u32(sWhi) + (uint32_t)(nBase + ((lane >> 4) << 3) + (lane & 7)) * 128;
    const uint32_t bCol = ((lane >> 3) & 1) * 16;

    // copy mapping: thread -> (row, 64B half), 4x uint4 each per tile
    const int cr = tid >> 1;           // 0..127
    const int ch = tid & 1;            // 0..1

    const __nv_bfloat16* gAh = Ahi + (size_t)(m0 + cr) * DIMD + ch * 32;
    const __nv_bfloat16* gAl = Alo + (size_t)(m0 + cr) * DIMD + ch * 32;
    const __nv_bfloat16* gWh = Whi + (size_t)(n0 + cr) * DIMD + ch * 32;
    const __nv_bfloat16* gWl = Wlo + (size_t)(n0 + cr) * DIMD + ch * 32;

    float c[4][4][4];
#pragma unroll
    for (int i = 0; i < 4; i++)
#pragma unroll
        for (int j = 0; j < 4; j++)
#pragma unroll
            for (int e = 0; e < 4; e++) c[i][j][e] = 0.f;

#pragma unroll 1
    for (int kc = 0; kc < DIMD / 64; ++kc) {
        __syncthreads();   // previous chunk's mma done reading smem
#pragma unroll
        for (int i = 0; i < 4; ++i) {
            uint32_t off = (uint32_t)cr * 128 + ch * 64 + i * 16;
            uint32_t sw  = off ^ ((off >> 3) & 0x70);
            const int e  = i * 8;      // bf16 elems within the 32-elem half
            *(uint4*)(sAhi + sw) = *(const uint4*)(gAh + kc * 64 + e);
            *(uint4*)(sAlo + sw) = *(const uint4*)(gAl + kc * 64 + e);
            *(uint4*)(sWhi + sw) = *(const uint4*)(gWh + kc * 64 + e);
            *(uint4*)(sWlo + sw) = *(const uint4*)(gWl + kc * 64 + e);
        }
        __syncthreads();

#pragma unroll
        for (int ks = 0; ks < 4; ++ks) {
            const uint32_t ca = ((uint32_t)(ks * 32) + aCol) ^ xork;
            const uint32_t cb = ((uint32_t)(ks * 32) + bCol) ^ xork;

            uint32_t ahi[4][4], alo[4][4], bhi[2][4], blo[2][4];
#pragma unroll
            for (int mf = 0; mf < 4; ++mf) {
                ldm_x4(ahi[mf], aRow + mf * 2048 + ca);
                ldm_x4(alo[mf], aRow + 16384u + mf * 2048 + ca);
            }
#pragma unroll
            for (int nh = 0; nh < 2; ++nh) {
                ldm_x4(bhi[nh], bRow + nh * 2048 + cb);
                ldm_x4(blo[nh], bRow + 16384u + nh * 2048 + cb);
            }

#pragma unroll
            for (int mf = 0; mf < 4; ++mf)
#pragma unroll
                for (int nf = 0; nf < 4; ++nf) {
                    const uint32_t* bh = &bhi[nf >> 1][(nf & 1) * 2];
                    const uint32_t* bl = &blo[nf >> 1][(nf & 1) * 2];
                    mma16816(c[mf][nf], ahi[mf], bh);
                    mma16816(c[mf][nf], ahi[mf], bl);
                    mma16816(c[mf][nf], alo[mf], bh);
                }
        }
    }

    // epilogue: c[mf][nf] regs -> rows mBase+mf*16+lane/4 (+8), col pairs
    const int rA = m0 + mBase + (lane >> 2);
    const int cA = n0 + nBase + (lane & 3) * 2;
#pragma unroll
    for (int mf = 0; mf < 4; ++mf)
#pragma unroll
        for (int nf = 0; nf < 4; ++nf) {
            const int row = rA + mf * 16;
            const int col = cA + nf * 8;
            const float b0 = bias[col], b1 = bias[col + 1];
            *(float2*)(C + (size_t)row * DIMD + col) =
                make_float2(c[mf][nf][0] + b0, c[mf][nf][1] + b1);
            *(float2*)(C + (size_t)(row + 8) * DIMD + col) =
                make_float2(c[mf][nf][2] + b0, c[mf][nf][3] + b1);
        }
}

__global__ void __launch_bounds__(256)
qkv_tc_kernel(const float* __restrict__ bq, const float* __restrict__ bk,
              const float* __restrict__ bv)
{
    const int z = blockIdx.z;
    const float* bias = (z == 0) ? bq : (z == 1) ? bk : bv;
    float* C = (z == 0) ? g_q : (z == 1) ? g_k : g_v;
    gemm_tc_body(g_xhi, g_xlo, g_whi + (size_t)z * WELEMS,
                 g_wlo + (size_t)z * WELEMS, bias, C);
}

__global__ void __launch_bounds__(256)
proj_tc_kernel(const float* __restrict__ bo, float* __restrict__ out)
{
    gemm_tc_body(g_ahi, g_alo, g_whi + 3ULL * WELEMS, g_wlo + 3ULL * WELEMS, bo, out);
}

// ---------------------------------------------------------------------------
// Attention: unchanged SIMT flash kernel; emits bf16 hi/lo for projection.
// ---------------------------------------------------------------------------
#define SQS 128
#define SVS 52
#define SPS 132
#define ATTN_SMEM_FLOATS (48*SQS + 48*SQS + 128*SVS + 128*SPS)
#define ATTN_SMEM_BYTES  (ATTN_SMEM_FLOATS * 4)

__global__ void __launch_bounds__(256, 1)
attn_kernel()
{
    extern __shared__ float sm[];
    float* sQ = sm;
    float* sK = sQ + 48 * SQS;
    float* sV = sK + 48 * SQS;
    float* sP = sV + 128 * SVS;

    const int tid  = threadIdx.x;
    const int tx   = tid & 15;
    const int ty   = tid >> 4;
    const int bid  = blockIdx.x;
    const int qt   = bid & 15;
    const size_t slab = (size_t)(bid >> 4) * (SEQ * HD);
    const int q0   = qt * 128;
    const int cx3  = tx * 3;

    {
        const int r  = tid & 127;
        const int hf = tid >> 7;
        const float* src = g_q + slab + (size_t)(q0 + r) * HD + hf * 24;
#pragma unroll
        for (int u = 0; u < 6; u++) {
            float4 v = *(const float4*)(src + u * 4);
            int d0 = hf * 24 + u * 4;
            sQ[(d0 + 0) * SQS + r] = v.x * SQRT48;
            sQ[(d0 + 1) * SQS + r] = v.y * SQRT48;
            sQ[(d0 + 2) * SQS + r] = v.z * SQRT48;
            sQ[(d0 + 3) * SQS + r] = v.w * SQRT48;
        }
    }

    float o[8][3];
    float mrow[8], lrow[8];
#pragma unroll
    for (int i = 0; i < 8; i++) {
        mrow[i] = -INFINITY; lrow[i] = 0.f;
        o[i][0] = o[i][1] = o[i][2] = 0.f;
    }

    for (int t = 0; t < SEQ / 128; ++t) {
        __syncthreads();

        {
            const int r  = tid & 127;
            const int hf = tid >> 7;
            const float* src = g_k + slab + (size_t)(t * 128 + r) * HD + hf * 24;
#pragma unroll
            for (int u = 0; u < 6; u++) {
                float4 v = *(const float4*)(src + u * 4);
                int d0 = hf * 24 + u * 4;
                sK[(d0 + 0) * SQS + r] = v.x;
                sK[(d0 + 1) * SQS + r] = v.y;
                sK[(d0 + 2) * SQS + r] = v.z;
                sK[(d0 + 3) * SQS + r] = v.w;
            }
        }
        {
            const float* vbase = g_v + slab + (size_t)(t * 128) * HD;
#pragma unroll
            for (int u = 0; u < 6; u++) {
                int fi = tid + 256 * u;
                int rr = fi / 12;
                int dq = fi - rr * 12;
                float4 v = *(const float4*)(vbase + rr * HD + dq * 4);
                *(float4*)(sV + rr * SVS + dq * 4) = v;
            }
        }
        __syncthreads();

        float acc[8][8];
#pragma unroll
        for (int i = 0; i < 8; i++)
#pragma unroll
            for (int j = 0; j < 8; j++) acc[i][j] = 0.f;

#pragma unroll 4
        for (int d = 0; d < HD; ++d) {
            float4 a0 = *(const float4*)(sQ + d * SQS + ty * 8);
            float4 a1 = *(const float4*)(sQ + d * SQS + ty * 8 + 4);
            float4 b0 = *(const float4*)(sK + d * SQS + tx * 8);
            float4 b1 = *(const float4*)(sK + d * SQS + tx * 8 + 4);
            float av[8] = {a0.x, a0.y, a0.z, a0.w, a1.x, a1.y, a1.z, a1.w};
            float bv[8] = {b0.x, b0.y, b0.z, b0.w, b1.x, b1.y, b1.z, b1.w};
#pragma unroll
            for (int i = 0; i < 8; i++)
#pragma unroll
                for (int j = 0; j < 8; j++)
                    acc[i][j] = fmaf(av[i], bv[j], acc[i][j]);
        }

#pragma unroll
        for (int i = 0; i < 8; i++) {
            float mt = acc[i][0];
#pragma unroll
            for (int j = 1; j < 8; j++) mt = fmaxf(mt, acc[i][j]);
            mt = fmaxf(mt, __shfl_xor_sync(0xffffffffu, mt, 1));
            mt = fmaxf(mt, __shfl_xor_sync(0xffffffffu, mt, 2));
            mt = fmaxf(mt, __shfl_xor_sync(0xffffffffu, mt, 4));
            mt = fmaxf(mt, __shfl_xor_sync(0xffffffffu, mt, 8));

            float mnew = fmaxf(mrow[i], mt);
            float fi   = __expf(mrow[i] - mnew);
            mrow[i] = mnew;

            float rs = 0.f;
#pragma unroll
            for (int j = 0; j < 8; j++) {
                float p = __expf(acc[i][j] - mnew);
                acc[i][j] = p;
                rs += p;
            }
            rs += __shfl_xor_sync(0xffffffffu, rs, 1);
            rs += __shfl_xor_sync(0xffffffffu, rs, 2);
            rs += __shfl_xor_sync(0xffffffffu, rs, 4);
            rs += __shfl_xor_sync(0xffffffffu, rs, 8);

            lrow[i] = lrow[i] * fi + rs;
            o[i][0] *= fi; o[i][1] *= fi; o[i][2] *= fi;

            *(float4*)(sP + (ty * 8 + i) * SPS + tx * 8) =
                make_float4(acc[i][0], acc[i][1], acc[i][2], acc[i][3]);
            *(float4*)(sP + (ty * 8 + i) * SPS + tx * 8 + 4) =
                make_float4(acc[i][4], acc[i][5], acc[i][6], acc[i][7]);
        }
        __syncthreads();

        const float* prow = sP + (size_t)(ty * 8) * SPS;
#pragma unroll 2
        for (int j = 0; j < 128; ++j) {
            float v0 = sV[j * SVS + cx3 + 0];
            float v1 = sV[j * SVS + cx3 + 1];
            float v2 = sV[j * SVS + cx3 + 2];
#pragma unroll
            for (int i = 0; i < 8; i++) {
                float p = prow[i * SPS + j];
                o[i][0] = fmaf(p, v0, o[i][0]);
                o[i][1] = fmaf(p, v1, o[i][1]);
                o[i][2] = fmaf(p, v2, o[i][2]);
            }
        }
    }

#pragma unroll
    for (int i = 0; i < 8; i++) {
        float inv = 1.f / lrow[i];
        size_t base = slab + (size_t)(q0 + ty * 8 + i) * HD + cx3;
#pragma unroll
        for (int j = 0; j < 3; j++) {
            float val = o[i][j] * inv;
            __nv_bfloat16 h = __float2bfloat16(val);
            g_ahi[base + j] = h;
            g_alo[base + j] = __float2bfloat16(val - __bfloat162float(h));
        }
    }
}

// ---------------------------------------------------------------------------
extern "C" void kernel_launch(void* const* d_in, const int* in_sizes, int n_in,
                              void* d_out, int out_size)
{
    const float* x  = (const float*)d_in[0];
    const float* Wq = (const float*)d_in[1];
    const float* bq = (const float*)d_in[2];
    const float* Wk = (const float*)d_in[3];
    const float* bk = (const float*)d_in[4];
    const float* Wv = (const float*)d_in[5];
    const float* bv = (const float*)d_in[6];
    const float* Wo = (const float*)d_in[7];
    const float* bo = (const float*)d_in[8];
    float* out = (float*)d_out;

    cudaFuncSetAttribute(attn_kernel, cudaFuncAttributeMaxDynamicSharedMemorySize,
                         ATTN_SMEM_BYTES);
    cudaFuncSetAttribute(qkv_tc_kernel, cudaFuncAttributeMaxDynamicSharedMemorySize,
                         GEMM_SMEM_BYTES);
    cudaFuncSetAttribute(proj_tc_kernel, cudaFuncAttributeMaxDynamicSharedMemorySize,
                         GEMM_SMEM_BYTES);

    convert_w_kernel<<<4 * WELEMS / 4 / 256, 256>>>(Wq, Wk, Wv, Wo);
    convert_x_kernel<<<MROWS * DIMD / 4 / 256, 256>>>(x);

    dim3 gqkv(DIMD / 128, MROWS / 128, 3);
    qkv_tc_kernel<<<gqkv, 256, GEMM_SMEM_BYTES>>>(bq, bk, bv);

    attn_kernel<<<(MROWS / 128) * NHEADS, 256, ATTN_SMEM_BYTES>>>();

    dim3 gproj(DIMD / 128, MROWS / 128);
    proj_tc_kernel<<<gproj, 256, GEMM_SMEM_BYTES>>>(bo, out);

    (void)in_sizes; (void)n_in; (void)out_size;
}

// round 6
// speedup vs baseline: 2.0950x; 1.7497x over previous
#include <cuda_runtime.h>
#include <cuda_bf16.h>
#include <math.h>
#include <stdint.h>

// Problem constants
#define DIMD   768
#define MROWS  8192          // B*N = 4*2048
#define NHEADS 16
#define HD     48
#define SEQ    2048
#define SQRT48 6.9282032302755091741f
#define WELEMS (DIMD * DIMD)

// ---------------------------------------------------------------------------
// Scratch (__device__ globals; no allocations anywhere)
// ---------------------------------------------------------------------------
__device__ __nv_bfloat16 g_xhi[MROWS * DIMD];
__device__ __nv_bfloat16 g_xlo[MROWS * DIMD];
__device__ __nv_bfloat16 g_qhi[MROWS * DIMD];   // pre-scaled by sqrt(48)
__device__ __nv_bfloat16 g_qlo[MROWS * DIMD];
__device__ __nv_bfloat16 g_khi[MROWS * DIMD];
__device__ __nv_bfloat16 g_klo[MROWS * DIMD];
__device__ __nv_bfloat16 g_vhi[MROWS * DIMD];
__device__ __nv_bfloat16 g_vlo[MROWS * DIMD];
__device__ __nv_bfloat16 g_ahi[MROWS * DIMD];
__device__ __nv_bfloat16 g_alo[MROWS * DIMD];
__device__ __nv_bfloat16 g_whi[4 * WELEMS];
__device__ __nv_bfloat16 g_wlo[4 * WELEMS];

// ---------------------------------------------------------------------------
// mma.sync helpers (baseline PTX — legal on plain sm_100 target)
// ---------------------------------------------------------------------------
__device__ __forceinline__ uint32_t smem_u32(const void* p) {
    uint32_t a;
    asm("{ .reg .u64 t; cvta.to.shared.u64 t, %1; cvt.u32.u64 %0, t; }"
        : "=r"(a) : "l"(p));
    return a;
}

__device__ __forceinline__ void ldm_x4(uint32_t* r, uint32_t addr) {
    asm volatile("ldmatrix.sync.aligned.m8n8.x4.shared.b16 {%0,%1,%2,%3}, [%4];"
                 : "=r"(r[0]), "=r"(r[1]), "=r"(r[2]), "=r"(r[3]) : "r"(addr));
}

__device__ __forceinline__ void ldm_x4_t(uint32_t* r, uint32_t addr) {
    asm volatile("ldmatrix.sync.aligned.m8n8.x4.trans.shared.b16 {%0,%1,%2,%3}, [%4];"
                 : "=r"(r[0]), "=r"(r[1]), "=r"(r[2]), "=r"(r[3]) : "r"(addr));
}

__device__ __forceinline__ void mma16816(float* c, const uint32_t* a,
                                         const uint32_t* b) {
    asm volatile(
        "mma.sync.aligned.m16n8k16.row.col.f32.bf16.bf16.f32 "
        "{%0,%1,%2,%3}, {%4,%5,%6,%7}, {%8,%9}, {%0,%1,%2,%3};"
        : "+f"(c[0]), "+f"(c[1]), "+f"(c[2]), "+f"(c[3])
        : "r"(a[0]), "r"(a[1]), "r"(a[2]), "r"(a[3]), "r"(b[0]), "r"(b[1]));
}

__device__ __forceinline__ uint32_t pack2(__nv_bfloat16 a, __nv_bfloat16 b) {
    __nv_bfloat162 t; t.x = a; t.y = b;
    return *(uint32_t*)&t;
}

__device__ __forceinline__ void split1(float v, __nv_bfloat16* hi, __nv_bfloat16* lo) {
    __nv_bfloat16 h = __float2bfloat16(v);
    *hi = h;
    *lo = __float2bfloat16(v - __bfloat162float(h));
}

__device__ __forceinline__ void store_split2(__nv_bfloat16* Chi, __nv_bfloat16* Clo,
                                             size_t idx, float a, float b) {
    __nv_bfloat16 ha = __float2bfloat16(a), hb = __float2bfloat16(b);
    __nv_bfloat162 hp; hp.x = ha; hp.y = hb;
    *(__nv_bfloat162*)(Chi + idx) = hp;
    __nv_bfloat162 lp;
    lp.x = __float2bfloat16(a - __bfloat162float(ha));
    lp.y = __float2bfloat16(b - __bfloat162float(hb));
    *(__nv_bfloat162*)(Clo + idx) = lp;
}

// ---------------------------------------------------------------------------
// Conversion kernels
// ---------------------------------------------------------------------------
__global__ void convert_x_kernel(const float* __restrict__ x) {
    int i4 = blockIdx.x * 256 + threadIdx.x;
    float4 v = ((const float4*)x)[i4];
    size_t b = (size_t)i4 * 4;
    split1(v.x, &g_xhi[b + 0], &g_xlo[b + 0]);
    split1(v.y, &g_xhi[b + 1], &g_xlo[b + 1]);
    split1(v.z, &g_xhi[b + 2], &g_xlo[b + 2]);
    split1(v.w, &g_xhi[b + 3], &g_xlo[b + 3]);
}

__global__ void convert_w_kernel(const float* __restrict__ Wq,
                                 const float* __restrict__ Wk,
                                 const float* __restrict__ Wv,
                                 const float* __restrict__ Wo) {
    int i4 = blockIdx.x * 256 + threadIdx.x;
    int per = WELEMS / 4;
    int mat = i4 / per;
    int off = i4 - mat * per;
    const float* src = (mat == 0) ? Wq : (mat == 1) ? Wk : (mat == 2) ? Wv : Wo;
    float4 v = ((const float4*)src)[off];
    size_t b = (size_t)mat * WELEMS + (size_t)off * 4;
    split1(v.x, &g_whi[b + 0], &g_wlo[b + 0]);
    split1(v.y, &g_whi[b + 1], &g_wlo[b + 1]);
    split1(v.z, &g_whi[b + 2], &g_wlo[b + 2]);
    split1(v.w, &g_whi[b + 3], &g_wlo[b + 3]);
}

// ---------------------------------------------------------------------------
// Split-bf16 GEMM via mma.sync (C = A @ W^T + bias), 128x128 tiles.
// SPLIT=true: write (C)*scale as bf16 hi/lo pair; else write f32.
// ---------------------------------------------------------------------------
#define GEMM_SMEM_BYTES (4 * 16384)

template <bool SPLIT>
__device__ __forceinline__ void gemm_tc_body(const __nv_bfloat16* __restrict__ Ahi,
                                             const __nv_bfloat16* __restrict__ Alo,
                                             const __nv_bfloat16* __restrict__ Whi,
                                             const __nv_bfloat16* __restrict__ Wlo,
                                             const float* __restrict__ bias,
                                             float* __restrict__ Cf,
                                             __nv_bfloat16* __restrict__ Chi,
                                             __nv_bfloat16* __restrict__ Clo,
                                             float scale)
{
    extern __shared__ char smem[];
    char* sAhi = smem;
    char* sAlo = smem + 16384;
    char* sWhi = smem + 32768;
    char* sWlo = smem + 49152;

    const int tid  = threadIdx.x;
    const int wid  = tid >> 5;
    const int lane = tid & 31;
    const int m0 = blockIdx.y * 128;
    const int n0 = blockIdx.x * 128;
    const int mBase = (wid >> 2) * 64;
    const int nBase = (wid & 3) * 32;

    const uint32_t xork = (lane & 7) * 16;
    const uint32_t aRow = smem_u32(sAhi) + (uint32_t)(mBase + (lane & 15)) * 128;
    const uint32_t aCol = ((lane >> 4) & 1) * 16;
    const uint32_t bRow = smem_u32(sWhi) + (uint32_t)(nBase + ((lane >> 4) << 3) + (lane & 7)) * 128;
    const uint32_t bCol = ((lane >> 3) & 1) * 16;

    const int cr = tid >> 1;
    const int ch = tid & 1;

    const __nv_bfloat16* gAh = Ahi + (size_t)(m0 + cr) * DIMD + ch * 32;
    const __nv_bfloat16* gAl = Alo + (size_t)(m0 + cr) * DIMD + ch * 32;
    const __nv_bfloat16* gWh = Whi + (size_t)(n0 + cr) * DIMD + ch * 32;
    const __nv_bfloat16* gWl = Wlo + (size_t)(n0 + cr) * DIMD + ch * 32;

    float c[4][4][4];
#pragma unroll
    for (int i = 0; i < 4; i++)
#pragma unroll
        for (int j = 0; j < 4; j++)
#pragma unroll
            for (int e = 0; e < 4; e++) c[i][j][e] = 0.f;

#pragma unroll 1
    for (int kc = 0; kc < DIMD / 64; ++kc) {
        __syncthreads();
#pragma unroll
        for (int i = 0; i < 4; ++i) {
            uint32_t off = (uint32_t)cr * 128 + ch * 64 + i * 16;
            uint32_t sw  = off ^ ((off >> 3) & 0x70);
            const int e  = i * 8;
            *(uint4*)(sAhi + sw) = *(const uint4*)(gAh + kc * 64 + e);
            *(uint4*)(sAlo + sw) = *(const uint4*)(gAl + kc * 64 + e);
            *(uint4*)(sWhi + sw) = *(const uint4*)(gWh + kc * 64 + e);
            *(uint4*)(sWlo + sw) = *(const uint4*)(gWl + kc * 64 + e);
        }
        __syncthreads();

#pragma unroll
        for (int ks = 0; ks < 4; ++ks) {
            const uint32_t ca = ((uint32_t)(ks * 32) + aCol) ^ xork;
            const uint32_t cb = ((uint32_t)(ks * 32) + bCol) ^ xork;

            uint32_t ahi[4][4], alo[4][4], bhi[2][4], blo[2][4];
#pragma unroll
            for (int mf = 0; mf < 4; ++mf) {
                ldm_x4(ahi[mf], aRow + mf * 2048 + ca);
                ldm_x4(alo[mf], aRow + 16384u + mf * 2048 + ca);
            }
#pragma unroll
            for (int nh = 0; nh < 2; ++nh) {
                ldm_x4(bhi[nh], bRow + nh * 2048 + cb);
                ldm_x4(blo[nh], bRow + 16384u + nh * 2048 + cb);
            }

#pragma unroll
            for (int mf = 0; mf < 4; ++mf)
#pragma unroll
                for (int nf = 0; nf < 4; ++nf) {
                    const uint32_t* bh = &bhi[nf >> 1][(nf & 1) * 2];
                    const uint32_t* bl = &blo[nf >> 1][(nf & 1) * 2];
                    mma16816(c[mf][nf], ahi[mf], bh);
                    mma16816(c[mf][nf], ahi[mf], bl);
                    mma16816(c[mf][nf], alo[mf], bh);
                }
        }
    }

    const int rA = m0 + mBase + (lane >> 2);
    const int cA = n0 + nBase + (lane & 3) * 2;
#pragma unroll
    for (int mf = 0; mf < 4; ++mf)
#pragma unroll
        for (int nf = 0; nf < 4; ++nf) {
            const int row = rA + mf * 16;
            const int col = cA + nf * 8;
            const float b0 = bias[col], b1 = bias[col + 1];
            float v00 = c[mf][nf][0] + b0, v01 = c[mf][nf][1] + b1;
            float v10 = c[mf][nf][2] + b0, v11 = c[mf][nf][3] + b1;
            if (SPLIT) {
                v00 *= scale; v01 *= scale; v10 *= scale; v11 *= scale;
                store_split2(Chi, Clo, (size_t)row * DIMD + col, v00, v01);
                store_split2(Chi, Clo, (size_t)(row + 8) * DIMD + col, v10, v11);
            } else {
                *(float2*)(Cf + (size_t)row * DIMD + col) = make_float2(v00, v01);
                *(float2*)(Cf + (size_t)(row + 8) * DIMD + col) = make_float2(v10, v11);
            }
        }
}

__global__ void __launch_bounds__(256)
qkv_tc_kernel(const float* __restrict__ bq, const float* __restrict__ bk,
              const float* __restrict__ bv)
{
    const int z = blockIdx.z;
    const float* bias = (z == 0) ? bq : (z == 1) ? bk : bv;
    __nv_bfloat16* Chi = (z == 0) ? g_qhi : (z == 1) ? g_khi : g_vhi;
    __nv_bfloat16* Clo = (z == 0) ? g_qlo : (z == 1) ? g_klo : g_vlo;
    const float scale = (z == 0) ? SQRT48 : 1.0f;
    gemm_tc_body<true>(g_xhi, g_xlo, g_whi + (size_t)z * WELEMS,
                       g_wlo + (size_t)z * WELEMS, bias, nullptr, Chi, Clo, scale);
}

__global__ void __launch_bounds__(256)
proj_tc_kernel(const float* __restrict__ bo, float* __restrict__ out)
{
    gemm_tc_body<false>(g_ahi, g_alo, g_whi + 3ULL * WELEMS, g_wlo + 3ULL * WELEMS,
                        bo, out, nullptr, nullptr, 1.0f);
}

// ---------------------------------------------------------------------------
// FlashAttention-2 via mma.sync, split-bf16 3-product for QK^T and PV.
// Block = (b, h, 128 q-rows); warp owns 16 q-rows x full k-width.
// Tiles in smem padded to 112B rows (conflict-free ldmatrix, no swizzle).
// P never leaves registers (S c-frags repack into PV a-frags).
// ---------------------------------------------------------------------------
#define ATS 112                     // bytes per padded tile row (56 bf16)
#define ATILE_BYTES (128 * ATS)     // 14336
#define ATTN_SMEM_BYTES (6 * ATILE_BYTES)

__global__ void __launch_bounds__(256)
attn_tc_kernel()
{
    extern __shared__ char smem[];
    char* sQh = smem;
    char* sQl = smem + ATILE_BYTES;
    char* sKh = smem + 2 * ATILE_BYTES;
    char* sKl = smem + 3 * ATILE_BYTES;
    char* sVh = smem + 4 * ATILE_BYTES;
    char* sVl = smem + 5 * ATILE_BYTES;

    const int tid  = threadIdx.x;
    const int wid  = tid >> 5;
    const int lane = tid & 31;
    const int bid  = blockIdx.x;
    const int qt   = bid & 15;
    const size_t slab = (size_t)(bid >> 4) * (SEQ * HD);
    const int q0   = qt * 128;

    const uint32_t sbase = smem_u32(smem);
    const uint32_t qOff = (uint32_t)((wid * 16 + (lane & 15)) * ATS + ((lane >> 4) & 1) * 16);
    const uint32_t kOff = (uint32_t)(((((lane >> 4) & 1) << 3) + (lane & 7)) * ATS + ((lane >> 3) & 1) * 16);
    const uint32_t vOff = (uint32_t)(((lane & 7) + ((lane >> 3) & 1) * 8) * ATS + ((lane >> 4) & 1) * 16);

    // ---- load Q tile (once): 128 rows x 48 bf16 contiguous -> padded smem
    {
        const uint4* gh = (const uint4*)(g_qhi + slab + (size_t)q0 * HD);
        const uint4* gl = (const uint4*)(g_qlo + slab + (size_t)q0 * HD);
#pragma unroll
        for (int u = 0; u < 3; ++u) {
            int gi = tid + u * 256;
            int r = gi / 6, j = gi - r * 6;
            int so = r * ATS + j * 16;
            *(uint4*)(sQh + so) = gh[gi];
            *(uint4*)(sQl + so) = gl[gi];
        }
    }

    float o[6][4];
#pragma unroll
    for (int i = 0; i < 6; i++)
#pragma unroll
        for (int e = 0; e < 4; e++) o[i][e] = 0.f;
    float m0r = -INFINITY, m1r = -INFINITY, l0 = 0.f, l1 = 0.f;

#pragma unroll 1
    for (int t = 0; t < SEQ / 128; ++t) {
        __syncthreads();
        {
            const size_t tb = slab + (size_t)(t * 128) * HD;
            const uint4* kh = (const uint4*)(g_khi + tb);
            const uint4* kl = (const uint4*)(g_klo + tb);
            const uint4* vh = (const uint4*)(g_vhi + tb);
            const uint4* vl = (const uint4*)(g_vlo + tb);
#pragma unroll
            for (int u = 0; u < 3; ++u) {
                int gi = tid + u * 256;
                int r = gi / 6, j = gi - r * 6;
                int so = r * ATS + j * 16;
                *(uint4*)(sKh + so) = kh[gi];
                *(uint4*)(sKl + so) = kl[gi];
                *(uint4*)(sVh + so) = vh[gi];
                *(uint4*)(sVl + so) = vl[gi];
            }
        }
        __syncthreads();

        // ---- S = Q K^T (warp: 16 rows x 128 cols), 3-product split
        float c[16][4];
#pragma unroll
        for (int i = 0; i < 16; i++)
#pragma unroll
            for (int e = 0; e < 4; e++) c[i][e] = 0.f;

#pragma unroll
        for (int ks = 0; ks < 3; ++ks) {
            uint32_t qh[4], ql[4];
            ldm_x4(qh, sbase + qOff + ks * 32);
            ldm_x4(ql, sbase + ATILE_BYTES + qOff + ks * 32);
#pragma unroll
            for (int ng = 0; ng < 8; ++ng) {
                uint32_t kh4[4], kl4[4];
                const uint32_t ka = sbase + 2 * ATILE_BYTES + kOff + ng * (16 * ATS) + ks * 32;
                ldm_x4(kh4, ka);
                ldm_x4(kl4, ka + ATILE_BYTES);
                mma16816(c[2 * ng],     qh, kh4);
                mma16816(c[2 * ng],     qh, kl4);
                mma16816(c[2 * ng],     ql, kh4);
                mma16816(c[2 * ng + 1], qh, kh4 + 2);
                mma16816(c[2 * ng + 1], qh, kl4 + 2);
                mma16816(c[2 * ng + 1], ql, kh4 + 2);
            }
        }

        // ---- online softmax (rows r=wid*16+(lane>>2) and r+8; quad shfl)
        float mt0 = c[0][0], mt1 = c[0][2];
#pragma unroll
        for (int nf = 0; nf < 16; ++nf) {
            mt0 = fmaxf(mt0, fmaxf(c[nf][0], c[nf][1]));
            mt1 = fmaxf(mt1, fmaxf(c[nf][2], c[nf][3]));
        }
        mt0 = fmaxf(mt0, __shfl_xor_sync(0xffffffffu, mt0, 1));
        mt0 = fmaxf(mt0, __shfl_xor_sync(0xffffffffu, mt0, 2));
        mt1 = fmaxf(mt1, __shfl_xor_sync(0xffffffffu, mt1, 1));
        mt1 = fmaxf(mt1, __shfl_xor_sync(0xffffffffu, mt1, 2));

        const float mn0 = fmaxf(m0r, mt0), mn1 = fmaxf(m1r, mt1);
        const float f0 = __expf(m0r - mn0), f1 = __expf(m1r - mn1);
        m0r = mn0; m1r = mn1;

        float rs0 = 0.f, rs1 = 0.f;
        uint32_t pH[16][2], pL[16][2];
#pragma unroll
        for (int nf = 0; nf < 16; ++nf) {
            float p0 = __expf(c[nf][0] - mn0);
            float p1 = __expf(c[nf][1] - mn0);
            float p2 = __expf(c[nf][2] - mn1);
            float p3 = __expf(c[nf][3] - mn1);
            rs0 += p0 + p1; rs1 += p2 + p3;
            __nv_bfloat16 h0 = __float2bfloat16(p0), h1 = __float2bfloat16(p1);
            __nv_bfloat16 h2 = __float2bfloat16(p2), h3 = __float2bfloat16(p3);
            pH[nf][0] = pack2(h0, h1);
            pH[nf][1] = pack2(h2, h3);
            pL[nf][0] = pack2(__float2bfloat16(p0 - __bfloat162float(h0)),
                              __float2bfloat16(p1 - __bfloat162float(h1)));
            pL[nf][1] = pack2(__float2bfloat16(p2 - __bfloat162float(h2)),
                              __float2bfloat16(p3 - __bfloat162float(h3)));
        }
        rs0 += __shfl_xor_sync(0xffffffffu, rs0, 1);
        rs0 += __shfl_xor_sync(0xffffffffu, rs0, 2);
        rs1 += __shfl_xor_sync(0xffffffffu, rs1, 1);
        rs1 += __shfl_xor_sync(0xffffffffu, rs1, 2);
        l0 = l0 * f0 + rs0;
        l1 = l1 * f1 + rs1;

#pragma unroll
        for (int nc = 0; nc < 6; ++nc) {
            o[nc][0] *= f0; o[nc][1] *= f0;
            o[nc][2] *= f1; o[nc][3] *= f1;
        }

        // ---- O += P V  (P from registers; V via ldmatrix.trans)
#pragma unroll
        for (int kk = 0; kk < 8; ++kk) {
            uint32_t aH[4] = {pH[2 * kk][0], pH[2 * kk][1], pH[2 * kk + 1][0], pH[2 * kk + 1][1]};
            uint32_t aL[4] = {pL[2 * kk][0], pL[2 * kk][1], pL[2 * kk + 1][0], pL[2 * kk + 1][1]};
#pragma unroll
            for (int nc = 0; nc < 3; ++nc) {
                uint32_t vh4[4], vl4[4];
                const uint32_t va = sbase + 4 * ATILE_BYTES + vOff + kk * (16 * ATS) + nc * 32;
                ldm_x4_t(vh4, va);
                ldm_x4_t(vl4, va + ATILE_BYTES);
                mma16816(o[2 * nc],     aH, vh4);
                mma16816(o[2 * nc],     aH, vl4);
                mma16816(o[2 * nc],     aL, vh4);
                mma16816(o[2 * nc + 1], aH, vh4 + 2);
                mma16816(o[2 * nc + 1], aH, vl4 + 2);
                mma16816(o[2 * nc + 1], aL, vh4 + 2);
            }
        }
    }

    // ---- finalize: /l, split-store to g_ahi/g_alo (raw-view layout)
    const float inv0 = 1.f / l0, inv1 = 1.f / l1;
    const int r0 = q0 + wid * 16 + (lane >> 2);
    const int cc = (lane & 3) * 2;
#pragma unroll
    for (int nf = 0; nf < 6; ++nf) {
        const int col = nf * 8 + cc;
        store_split2(g_ahi, g_alo, slab + (size_t)r0 * HD + col,
                     o[nf][0] * inv0, o[nf][1] * inv0);
        store_split2(g_ahi, g_alo, slab + (size_t)(r0 + 8) * HD + col,
                     o[nf][2] * inv1, o[nf][3] * inv1);
    }
}

// ---------------------------------------------------------------------------
extern "C" void kernel_launch(void* const* d_in, const int* in_sizes, int n_in,
                              void* d_out, int out_size)
{
    const float* x  = (const float*)d_in[0];
    const float* Wq = (const float*)d_in[1];
    const float* bq = (const float*)d_in[2];
    const float* Wk = (const float*)d_in[3];
    const float* bk = (const float*)d_in[4];
    const float* Wv = (const float*)d_in[5];
    const float* bv = (const float*)d_in[6];
    const float* Wo = (const float*)d_in[7];
    const float* bo = (const float*)d_in[8];
    float* out = (float*)d_out;

    cudaFuncSetAttribute(attn_tc_kernel, cudaFuncAttributeMaxDynamicSharedMemorySize,
                         ATTN_SMEM_BYTES);
    cudaFuncSetAttribute(qkv_tc_kernel, cudaFuncAttributeMaxDynamicSharedMemorySize,
                         GEMM_SMEM_BYTES);
    cudaFuncSetAttribute(proj_tc_kernel, cudaFuncAttributeMaxDynamicSharedMemorySize,
                         GEMM_SMEM_BYTES);

    convert_w_kernel<<<4 * WELEMS / 4 / 256, 256>>>(Wq, Wk, Wv, Wo);
    convert_x_kernel<<<MROWS * DIMD / 4 / 256, 256>>>(x);

    dim3 gqkv(DIMD / 128, MROWS / 128, 3);
    qkv_tc_kernel<<<gqkv, 256, GEMM_SMEM_BYTES>>>(bq, bk, bv);

    attn_tc_kernel<<<(MROWS / 128) * NHEADS, 256, ATTN_SMEM_BYTES>>>();

    dim3 gproj(DIMD / 128, MROWS / 128);
    proj_tc_kernel<<<gproj, 256, GEMM_SMEM_BYTES>>>(bo, out);

    (void)in_sizes; (void)n_in; (void)out_size;
}

// round 8
// speedup vs baseline: 2.4906x; 1.1888x over previous
#include <cuda_runtime.h>
#include <cuda_bf16.h>
#include <math.h>
#include <stdint.h>

// Problem constants
#define DIMD   768
#define MROWS  8192          // B*N = 4*2048
#define NHEADS 16
#define HD     48
#define SEQ    2048
#define SQRT48 6.9282032302755091741f
#define LOG2E  1.4426950408889634074f
#define WELEMS (DIMD * DIMD)

// ---------------------------------------------------------------------------
// Scratch (__device__ globals; no allocations anywhere)
// ---------------------------------------------------------------------------
__device__ __nv_bfloat16 g_xhi[MROWS * DIMD];
__device__ __nv_bfloat16 g_xlo[MROWS * DIMD];
__device__ __nv_bfloat16 g_qhi[MROWS * DIMD];   // pre-scaled by sqrt(48)*log2e
__device__ __nv_bfloat16 g_qlo[MROWS * DIMD];
__device__ __nv_bfloat16 g_khi[MROWS * DIMD];
__device__ __nv_bfloat16 g_klo[MROWS * DIMD];
__device__ __nv_bfloat16 g_vhi[MROWS * DIMD];
__device__ __nv_bfloat16 g_vlo[MROWS * DIMD];
__device__ __nv_bfloat16 g_ahi[MROWS * DIMD];
__device__ __nv_bfloat16 g_alo[MROWS * DIMD];
__device__ __nv_bfloat16 g_whi[4 * WELEMS];
__device__ __nv_bfloat16 g_wlo[4 * WELEMS];

// ---------------------------------------------------------------------------
// mma.sync helpers (baseline PTX — legal on plain sm_100 target)
// ---------------------------------------------------------------------------
__device__ __forceinline__ uint32_t smem_u32(const void* p) {
    uint32_t a;
    asm("{ .reg .u64 t; cvta.to.shared.u64 t, %1; cvt.u32.u64 %0, t; }"
        : "=r"(a) : "l"(p));
    return a;
}

__device__ __forceinline__ void ldm_x4(uint32_t* r, uint32_t addr) {
    asm volatile("ldmatrix.sync.aligned.m8n8.x4.shared.b16 {%0,%1,%2,%3}, [%4];"
                 : "=r"(r[0]), "=r"(r[1]), "=r"(r[2]), "=r"(r[3]) : "r"(addr));
}

__device__ __forceinline__ void ldm_x4_t(uint32_t* r, uint32_t addr) {
    asm volatile("ldmatrix.sync.aligned.m8n8.x4.trans.shared.b16 {%0,%1,%2,%3}, [%4];"
                 : "=r"(r[0]), "=r"(r[1]), "=r"(r[2]), "=r"(r[3]) : "r"(addr));
}

__device__ __forceinline__ void mma16816(float* c, const uint32_t* a,
                                         const uint32_t* b) {
    asm volatile(
        "mma.sync.aligned.m16n8k16.row.col.f32.bf16.bf16.f32 "
        "{%0,%1,%2,%3}, {%4,%5,%6,%7}, {%8,%9}, {%0,%1,%2,%3};"
        : "+f"(c[0]), "+f"(c[1]), "+f"(c[2]), "+f"(c[3])
        : "r"(a[0]), "r"(a[1]), "r"(a[2]), "r"(a[3]), "r"(b[0]), "r"(b[1]));
}

__device__ __forceinline__ uint32_t pack2(__nv_bfloat16 a, __nv_bfloat16 b) {
    __nv_bfloat162 t; t.x = a; t.y = b;
    return *(uint32_t*)&t;
}

__device__ __forceinline__ void split1(float v, __nv_bfloat16* hi, __nv_bfloat16* lo) {
    __nv_bfloat16 h = __float2bfloat16(v);
    *hi = h;
    *lo = __float2bfloat16(v - __bfloat162float(h));
}

__device__ __forceinline__ void store_split2(__nv_bfloat16* Chi, __nv_bfloat16* Clo,
                                             size_t idx, float a, float b) {
    __nv_bfloat16 ha = __float2bfloat16(a), hb = __float2bfloat16(b);
    __nv_bfloat162 hp; hp.x = ha; hp.y = hb;
    *(__nv_bfloat162*)(Chi + idx) = hp;
    __nv_bfloat162 lp;
    lp.x = __float2bfloat16(a - __bfloat162float(ha));
    lp.y = __float2bfloat16(b - __bfloat162float(hb));
    *(__nv_bfloat162*)(Clo + idx) = lp;
}

// ---------------------------------------------------------------------------
// Conversion kernels
// ---------------------------------------------------------------------------
__global__ void convert_x_kernel(const float* __restrict__ x) {
    int i4 = blockIdx.x * 256 + threadIdx.x;
    float4 v = ((const float4*)x)[i4];
    size_t b = (size_t)i4 * 4;
    split1(v.x, &g_xhi[b + 0], &g_xlo[b + 0]);
    split1(v.y, &g_xhi[b + 1], &g_xlo[b + 1]);
    split1(v.z, &g_xhi[b + 2], &g_xlo[b + 2]);
    split1(v.w, &g_xhi[b + 3], &g_xlo[b + 3]);
}

__global__ void convert_w_kernel(const float* __restrict__ Wq,
                                 const float* __restrict__ Wk,
                                 const float* __restrict__ Wv,
                                 const float* __restrict__ Wo) {
    int i4 = blockIdx.x * 256 + threadIdx.x;
    int per = WELEMS / 4;
    int mat = i4 / per;
    int off = i4 - mat * per;
    const float* src = (mat == 0) ? Wq : (mat == 1) ? Wk : (mat == 2) ? Wv : Wo;
    float4 v = ((const float4*)src)[off];
    size_t b = (size_t)mat * WELEMS + (size_t)off * 4;
    split1(v.x, &g_whi[b + 0], &g_wlo[b + 0]);
    split1(v.y, &g_whi[b + 1], &g_wlo[b + 1]);
    split1(v.z, &g_whi[b + 2], &g_wlo[b + 2]);
    split1(v.w, &g_whi[b + 3], &g_wlo[b + 3]);
}

// ---------------------------------------------------------------------------
// Split-bf16 GEMM via mma.sync (C = A @ W^T + bias), 128x128 tiles.
// ---------------------------------------------------------------------------
#define GEMM_SMEM_BYTES (4 * 16384)

template <bool SPLIT>
__device__ __forceinline__ void gemm_tc_body(const __nv_bfloat16* __restrict__ Ahi,
                                             const __nv_bfloat16* __restrict__ Alo,
                                             const __nv_bfloat16* __restrict__ Whi,
                                             const __nv_bfloat16* __restrict__ Wlo,
                                             const float* __restrict__ bias,
                                             float* __restrict__ Cf,
                                             __nv_bfloat16* __restrict__ Chi,
                                             __nv_bfloat16* __restrict__ Clo,
                                             float scale)
{
    extern __shared__ char smem[];
    char* sAhi = smem;
    char* sWhi = smem + 32768;

    const int tid  = threadIdx.x;
    const int wid  = tid >> 5;
    const int lane = tid & 31;
    const int m0 = blockIdx.y * 128;
    const int n0 = blockIdx.x * 128;
    const int mBase = (wid >> 2) * 64;
    const int nBase = (wid & 3) * 32;

    const uint32_t xork = (lane & 7) * 16;
    const uint32_t aRow = smem_u32(sAhi) + (uint32_t)(mBase + (lane & 15)) * 128;
    const uint32_t aCol = ((lane >> 4) & 1) * 16;
    const uint32_t bRow = smem_u32(sWhi) + (uint32_t)(nBase + ((lane >> 4) << 3) + (lane & 7)) * 128;
    const uint32_t bCol = ((lane >> 3) & 1) * 16;

    const int cr = tid >> 1;
    const int ch = tid & 1;

    const __nv_bfloat16* gAh = Ahi + (size_t)(m0 + cr) * DIMD + ch * 32;
    const __nv_bfloat16* gAl = Alo + (size_t)(m0 + cr) * DIMD + ch * 32;
    const __nv_bfloat16* gWh = Whi + (size_t)(n0 + cr) * DIMD + ch * 32;
    const __nv_bfloat16* gWl = Wlo + (size_t)(n0 + cr) * DIMD + ch * 32;

    float c[4][4][4];
#pragma unroll
    for (int i = 0; i < 4; i++)
#pragma unroll
        for (int j = 0; j < 4; j++)
#pragma unroll
            for (int e = 0; e < 4; e++) c[i][j][e] = 0.f;

#pragma unroll 1
    for (int kc = 0; kc < DIMD / 64; ++kc) {
        __syncthreads();
#pragma unroll
        for (int i = 0; i < 4; ++i) {
            uint32_t off = (uint32_t)cr * 128 + ch * 64 + i * 16;
            uint32_t sw  = off ^ ((off >> 3) & 0x70);
            const int e  = i * 8;
            *(uint4*)(sAhi + sw) = *(const uint4*)(gAh + kc * 64 + e);
            *(uint4*)(sAhi + 16384 + sw) = *(const uint4*)(gAl + kc * 64 + e);
            *(uint4*)(sWhi + sw) = *(const uint4*)(gWh + kc * 64 + e);
            *(uint4*)(sWhi + 16384 + sw) = *(const uint4*)(gWl + kc * 64 + e);
        }
        __syncthreads();

#pragma unroll
        for (int ks = 0; ks < 4; ++ks) {
            const uint32_t ca = ((uint32_t)(ks * 32) + aCol) ^ xork;
            const uint32_t cb = ((uint32_t)(ks * 32) + bCol) ^ xork;

            uint32_t ahi[4][4], alo[4][4], bhi[2][4], blo[2][4];
#pragma unroll
            for (int mf = 0; mf < 4; ++mf) {
                ldm_x4(ahi[mf], aRow + mf * 2048 + ca);
                ldm_x4(alo[mf], aRow + 16384u + mf * 2048 + ca);
            }
#pragma unroll
            for (int nh = 0; nh < 2; ++nh) {
                ldm_x4(bhi[nh], bRow + nh * 2048 + cb);
                ldm_x4(blo[nh], bRow + 16384u + nh * 2048 + cb);
            }

#pragma unroll
            for (int mf = 0; mf < 4; ++mf)
#pragma unroll
                for (int nf = 0; nf < 4; ++nf) {
                    const uint32_t* bh = &bhi[nf >> 1][(nf & 1) * 2];
                    const uint32_t* bl = &blo[nf >> 1][(nf & 1) * 2];
                    mma16816(c[mf][nf], ahi[mf], bh);
                    mma16816(c[mf][nf], ahi[mf], bl);
                    mma16816(c[mf][nf], alo[mf], bh);
                }
        }
    }

    const int rA = m0 + mBase + (lane >> 2);
    const int cA = n0 + nBase + (lane & 3) * 2;
#pragma unroll
    for (int mf = 0; mf < 4; ++mf)
#pragma unroll
        for (int nf = 0; nf < 4; ++nf) {
            const int row = rA + mf * 16;
            const int col = cA + nf * 8;
            const float b0 = bias[col], b1 = bias[col + 1];
            float v00 = c[mf][nf][0] + b0, v01 = c[mf][nf][1] + b1;
            float v10 = c[mf][nf][2] + b0, v11 = c[mf][nf][3] + b1;
            if (SPLIT) {
                v00 *= scale; v01 *= scale; v10 *= scale; v11 *= scale;
                store_split2(Chi, Clo, (size_t)row * DIMD + col, v00, v01);
                store_split2(Chi, Clo, (size_t)(row + 8) * DIMD + col, v10, v11);
            } else {
                *(float2*)(Cf + (size_t)row * DIMD + col) = make_float2(v00, v01);
                *(float2*)(Cf + (size_t)(row + 8) * DIMD + col) = make_float2(v10, v11);
            }
        }
}

__global__ void __launch_bounds__(256)
qkv_tc_kernel(const float* __restrict__ bq, const float* __restrict__ bk,
              const float* __restrict__ bv)
{
    const int z = blockIdx.z;
    const float* bias = (z == 0) ? bq : (z == 1) ? bk : bv;
    __nv_bfloat16* Chi = (z == 0) ? g_qhi : (z == 1) ? g_khi : g_vhi;
    __nv_bfloat16* Clo = (z == 0) ? g_qlo : (z == 1) ? g_klo : g_vlo;
    const float scale = (z == 0) ? SQRT48 * LOG2E : 1.0f;   // fold log2e -> exp2
    gemm_tc_body<true>(g_xhi, g_xlo, g_whi + (size_t)z * WELEMS,
                       g_wlo + (size_t)z * WELEMS, bias, nullptr, Chi, Clo, scale);
}

__global__ void __launch_bounds__(256)
proj_tc_kernel(const float* __restrict__ bo, float* __restrict__ out)
{
    gemm_tc_body<false>(g_ahi, g_alo, g_whi + 3ULL * WELEMS, g_wlo + 3ULL * WELEMS,
                        bo, out, nullptr, nullptr, 1.0f);
}

// ---------------------------------------------------------------------------
// FlashAttention-2 via mma.sync, split-bf16, 64-col inner chunks.
// Register diet (<=128) -> 2 CTAs/SM. Logits are base-2 (log2e pre-folded).
// ---------------------------------------------------------------------------
#define ATS 112                     // bytes per padded tile row (56 bf16)
#define ATILE_BYTES (128 * ATS)     // 14336
#define ATTN_SMEM_BYTES (6 * ATILE_BYTES)

__global__ void __launch_bounds__(256, 2)
attn_tc_kernel()
{
    extern __shared__ char smem[];

    const int tid  = threadIdx.x;
    const int wid  = tid >> 5;
    const int lane = tid & 31;
    const int bid  = blockIdx.x;
    const int qt   = bid & 15;
    const size_t slab = (size_t)(bid >> 4) * (SEQ * HD);
    const int q0   = qt * 128;

    const uint32_t sbase = smem_u32(smem);
    const uint32_t qOff = (uint32_t)((wid * 16 + (lane & 15)) * ATS + ((lane >> 4) & 1) * 16);
    const uint32_t kOff = (uint32_t)(((((lane >> 4) & 1) << 3) + (lane & 7)) * ATS + ((lane >> 3) & 1) * 16);
    const uint32_t vOff = (uint32_t)(((lane & 7) + ((lane >> 3) & 1) * 8) * ATS + ((lane >> 4) & 1) * 16);

    // ---- load Q tile (once)
    {
        const uint4* gh = (const uint4*)(g_qhi + slab + (size_t)q0 * HD);
        const uint4* gl = (const uint4*)(g_qlo + slab + (size_t)q0 * HD);
#pragma unroll
        for (int u = 0; u < 3; ++u) {
            int gi = tid + u * 256;
            int r = gi / 6, j = gi - r * 6;
            int so = r * ATS + j * 16;
            *(uint4*)(smem + so) = gh[gi];
            *(uint4*)(smem + ATILE_BYTES + so) = gl[gi];
        }
    }

    float o[6][4];
#pragma unroll
    for (int i = 0; i < 6; i++)
#pragma unroll
        for (int e = 0; e < 4; e++) o[i][e] = 0.f;
    float m0r = -INFINITY, m1r = -INFINITY, l0 = 0.f, l1 = 0.f;

#pragma unroll 1
    for (int t = 0; t < SEQ / 128; ++t) {
        __syncthreads();
        {
            const size_t tb = slab + (size_t)(t * 128) * HD;
            const uint4* kh = (const uint4*)(g_khi + tb);
            const uint4* kl = (const uint4*)(g_klo + tb);
            const uint4* vh = (const uint4*)(g_vhi + tb);
            const uint4* vl = (const uint4*)(g_vlo + tb);
#pragma unroll
            for (int u = 0; u < 3; ++u) {
                int gi = tid + u * 256;
                int r = gi / 6, j = gi - r * 6;
                int so = r * ATS + j * 16;
                *(uint4*)(smem + 2 * ATILE_BYTES + so) = kh[gi];
                *(uint4*)(smem + 3 * ATILE_BYTES + so) = kl[gi];
                *(uint4*)(smem + 4 * ATILE_BYTES + so) = vh[gi];
                *(uint4*)(smem + 5 * ATILE_BYTES + so) = vl[gi];
            }
        }
        __syncthreads();

#pragma unroll 1
        for (int h = 0; h < 2; ++h) {
            // ---- S chunk: 16 q-rows x 64 k-cols, 3-product split
            float c[8][4];
#pragma unroll
            for (int i = 0; i < 8; i++)
#pragma unroll
                for (int e = 0; e < 4; e++) c[i][e] = 0.f;

#pragma unroll
            for (int ks = 0; ks < 3; ++ks) {
                uint32_t qh[4], ql[4];
                ldm_x4(qh, sbase + qOff + ks * 32);
                ldm_x4(ql, sbase + ATILE_BYTES + qOff + ks * 32);
#pragma unroll
                for (int ng = 0; ng < 4; ++ng) {
                    uint32_t kh4[4], kl4[4];
                    const uint32_t ka = sbase + 2 * ATILE_BYTES + kOff
                                      + (uint32_t)(h * 64 + ng * 16) * ATS + ks * 32;
                    ldm_x4(kh4, ka);
                    ldm_x4(kl4, ka + ATILE_BYTES);
                    mma16816(c[2 * ng],     qh, kh4);
                    mma16816(c[2 * ng],     qh, kl4);
                    mma16816(c[2 * ng],     ql, kh4);
                    mma16816(c[2 * ng + 1], qh, kh4 + 2);
                    mma16816(c[2 * ng + 1], qh, kl4 + 2);
                    mma16816(c[2 * ng + 1], ql, kh4 + 2);
                }
            }

            // ---- online softmax over this 64-col chunk (base-2 logits)
            float mt0 = c[0][0], mt1 = c[0][2];
#pragma unroll
            for (int nf = 0; nf < 8; ++nf) {
                mt0 = fmaxf(mt0, fmaxf(c[nf][0], c[nf][1]));
                mt1 = fmaxf(mt1, fmaxf(c[nf][2], c[nf][3]));
            }
            mt0 = fmaxf(mt0, __shfl_xor_sync(0xffffffffu, mt0, 1));
            mt0 = fmaxf(mt0, __shfl_xor_sync(0xffffffffu, mt0, 2));
            mt1 = fmaxf(mt1, __shfl_xor_sync(0xffffffffu, mt1, 1));
            mt1 = fmaxf(mt1, __shfl_xor_sync(0xffffffffu, mt1, 2));

            const float mn0 = fmaxf(m0r, mt0), mn1 = fmaxf(m1r, mt1);
            const float f0 = exp2f(m0r - mn0), f1 = exp2f(m1r - mn1);
            m0r = mn0; m1r = mn1;

            float rs0 = 0.f, rs1 = 0.f;
            uint32_t pH[8][2], pL[8][2];
#pragma unroll
            for (int nf = 0; nf < 8; ++nf) {
                float p0 = exp2f(c[nf][0] - mn0);
                float p1 = exp2f(c[nf][1] - mn0);
                float p2 = exp2f(c[nf][2] - mn1);
                float p3 = exp2f(c[nf][3] - mn1);
                rs0 += p0 + p1; rs1 += p2 + p3;
                __nv_bfloat16 h0 = __float2bfloat16(p0), h1 = __float2bfloat16(p1);
                __nv_bfloat16 h2 = __float2bfloat16(p2), h3 = __float2bfloat16(p3);
                pH[nf][0] = pack2(h0, h1);
                pH[nf][1] = pack2(h2, h3);
                pL[nf][0] = pack2(__float2bfloat16(p0 - __bfloat162float(h0)),
                                  __float2bfloat16(p1 - __bfloat162float(h1)));
                pL[nf][1] = pack2(__float2bfloat16(p2 - __bfloat162float(h2)),
                                  __float2bfloat16(p3 - __bfloat162float(h3)));
            }
            rs0 += __shfl_xor_sync(0xffffffffu, rs0, 1);
            rs0 += __shfl_xor_sync(0xffffffffu, rs0, 2);
            rs1 += __shfl_xor_sync(0xffffffffu, rs1, 1);
            rs1 += __shfl_xor_sync(0xffffffffu, rs1, 2);
            l0 = l0 * f0 + rs0;
            l1 = l1 * f1 + rs1;

#pragma unroll
            for (int nc = 0; nc < 6; ++nc) {
                o[nc][0] *= f0; o[nc][1] *= f0;
                o[nc][2] *= f1; o[nc][3] *= f1;
            }

            // ---- O += P V over this 64-row V chunk
#pragma unroll
            for (int kk = 0; kk < 4; ++kk) {
                uint32_t aH[4] = {pH[2 * kk][0], pH[2 * kk][1],
                                  pH[2 * kk + 1][0], pH[2 * kk + 1][1]};
                uint32_t aL[4] = {pL[2 * kk][0], pL[2 * kk][1],
                                  pL[2 * kk + 1][0], pL[2 * kk + 1][1]};
#pragma unroll
                for (int nc = 0; nc < 3; ++nc) {
                    uint32_t vh4[4], vl4[4];
                    const uint32_t va = sbase + 4 * ATILE_BYTES + vOff
                                      + (uint32_t)(h * 64 + kk * 16) * ATS + nc * 32;
                    ldm_x4_t(vh4, va);
                    ldm_x4_t(vl4, va + ATILE_BYTES);
                    mma16816(o[2 * nc],     aH, vh4);
                    mma16816(o[2 * nc],     aH, vl4);
                    mma16816(o[2 * nc],     aL, vh4);
                    mma16816(o[2 * nc + 1], aH, vh4 + 2);
                    mma16816(o[2 * nc + 1], aH, vl4 + 2);
                    mma16816(o[2 * nc + 1], aL, vh4 + 2);
                }
            }
        }
    }

    // ---- finalize: /l, split-store to g_ahi/g_alo (raw-view layout)
    const float inv0 = 1.f / l0, inv1 = 1.f / l1;
    const int r0 = q0 + wid * 16 + (lane >> 2);
    const int cc = (lane & 3) * 2;
#pragma unroll
    for (int nf = 0; nf < 6; ++nf) {
        const int col = nf * 8 + cc;
        store_split2(g_ahi, g_alo, slab + (size_t)r0 * HD + col,
                     o[nf][0] * inv0, o[nf][1] * inv0);
        store_split2(g_ahi, g_alo, slab + (size_t)(r0 + 8) * HD + col,
                     o[nf][2] * inv1, o[nf][3] * inv1);
    }
}

// ---------------------------------------------------------------------------
extern "C" void kernel_launch(void* const* d_in, const int* in_sizes, int n_in,
                              void* d_out, int out_size)
{
    const float* x  = (const float*)d_in[0];
    const float* Wq = (const float*)d_in[1];
    const float* bq = (const float*)d_in[2];
    const float* Wk = (const float*)d_in[3];
    const float* bk = (const float*)d_in[4];
    const float* Wv = (const float*)d_in[5];
    const float* bv = (const float*)d_in[6];
    const float* Wo = (const float*)d_in[7];
    const float* bo = (const float*)d_in[8];
    float* out = (float*)d_out;

    cudaFuncSetAttribute(attn_tc_kernel, cudaFuncAttributeMaxDynamicSharedMemorySize,
                         ATTN_SMEM_BYTES);
    cudaFuncSetAttribute(qkv_tc_kernel, cudaFuncAttributeMaxDynamicSharedMemorySize,
                         GEMM_SMEM_BYTES);
    cudaFuncSetAttribute(proj_tc_kernel, cudaFuncAttributeMaxDynamicSharedMemorySize,
                         GEMM_SMEM_BYTES);

    convert_w_kernel<<<4 * WELEMS / 4 / 256, 256>>>(Wq, Wk, Wv, Wo);
    convert_x_kernel<<<MROWS * DIMD / 4 / 256, 256>>>(x);

    dim3 gqkv(DIMD / 128, MROWS / 128, 3);
    qkv_tc_kernel<<<gqkv, 256, GEMM_SMEM_BYTES>>>(bq, bk, bv);

    attn_tc_kernel<<<(MROWS / 128) * NHEADS, 256, ATTN_SMEM_BYTES>>>();

    dim3 gproj(DIMD / 128, MROWS / 128);
    proj_tc_kernel<<<gproj, 256, GEMM_SMEM_BYTES>>>(bo, out);

    (void)in_sizes; (void)n_in; (void)out_size;
}

// round 9
// speedup vs baseline: 2.7116x; 1.0887x over previous
#include <cuda_runtime.h>
#include <cuda_bf16.h>
#include <math.h>
#include <stdint.h>

// Problem constants
#define DIMD   768
#define MROWS  8192          // B*N = 4*2048
#define NHEADS 16
#define HD     48
#define SEQ    2048
#define SQRT48 6.9282032302755091741f
#define LOG2E  1.4426950408889634074f
#define WELEMS (DIMD * DIMD)

// ---------------------------------------------------------------------------
// Scratch (__device__ globals; no allocations anywhere)
// ---------------------------------------------------------------------------
__device__ __nv_bfloat16 g_xhi[MROWS * DIMD];
__device__ __nv_bfloat16 g_xlo[MROWS * DIMD];
__device__ __nv_bfloat16 g_qhi[MROWS * DIMD];   // pre-scaled by sqrt(48)*log2e
__device__ __nv_bfloat16 g_qlo[MROWS * DIMD];
__device__ __nv_bfloat16 g_khi[MROWS * DIMD];
__device__ __nv_bfloat16 g_klo[MROWS * DIMD];
__device__ __nv_bfloat16 g_vhi[MROWS * DIMD];
__device__ __nv_bfloat16 g_vlo[MROWS * DIMD];
__device__ __nv_bfloat16 g_ahi[MROWS * DIMD];
__device__ __nv_bfloat16 g_alo[MROWS * DIMD];
__device__ __nv_bfloat16 g_whi[4 * WELEMS];
__device__ __nv_bfloat16 g_wlo[4 * WELEMS];

// ---------------------------------------------------------------------------
// mma.sync helpers (baseline PTX — legal on plain sm_100 target)
// ---------------------------------------------------------------------------
__device__ __forceinline__ uint32_t smem_u32(const void* p) {
    uint32_t a;
    asm("{ .reg .u64 t; cvta.to.shared.u64 t, %1; cvt.u32.u64 %0, t; }"
        : "=r"(a) : "l"(p));
    return a;
}

__device__ __forceinline__ void ldm_x4(uint32_t* r, uint32_t addr) {
    asm volatile("ldmatrix.sync.aligned.m8n8.x4.shared.b16 {%0,%1,%2,%3}, [%4];"
                 : "=r"(r[0]), "=r"(r[1]), "=r"(r[2]), "=r"(r[3]) : "r"(addr));
}

__device__ __forceinline__ void ldm_x4_t(uint32_t* r, uint32_t addr) {
    asm volatile("ldmatrix.sync.aligned.m8n8.x4.trans.shared.b16 {%0,%1,%2,%3}, [%4];"
                 : "=r"(r[0]), "=r"(r[1]), "=r"(r[2]), "=r"(r[3]) : "r"(addr));
}

__device__ __forceinline__ void mma16816(float* c, const uint32_t* a,
                                         const uint32_t* b) {
    asm volatile(
        "mma.sync.aligned.m16n8k16.row.col.f32.bf16.bf16.f32 "
        "{%0,%1,%2,%3}, {%4,%5,%6,%7}, {%8,%9}, {%0,%1,%2,%3};"
        : "+f"(c[0]), "+f"(c[1]), "+f"(c[2]), "+f"(c[3])
        : "r"(a[0]), "r"(a[1]), "r"(a[2]), "r"(a[3]), "r"(b[0]), "r"(b[1]));
}

__device__ __forceinline__ uint32_t pack2(__nv_bfloat16 a, __nv_bfloat16 b) {
    __nv_bfloat162 t; t.x = a; t.y = b;
    return *(uint32_t*)&t;
}

__device__ __forceinline__ void split1(float v, __nv_bfloat16* hi, __nv_bfloat16* lo) {
    __nv_bfloat16 h = __float2bfloat16(v);
    *hi = h;
    *lo = __float2bfloat16(v - __bfloat162float(h));
}

__device__ __forceinline__ void store_split2(__nv_bfloat16* Chi, __nv_bfloat16* Clo,
                                             size_t idx, float a, float b) {
    __nv_bfloat16 ha = __float2bfloat16(a), hb = __float2bfloat16(b);
    __nv_bfloat162 hp; hp.x = ha; hp.y = hb;
    *(__nv_bfloat162*)(Chi + idx) = hp;
    __nv_bfloat162 lp;
    lp.x = __float2bfloat16(a - __bfloat162float(ha));
    lp.y = __float2bfloat16(b - __bfloat162float(hb));
    *(__nv_bfloat162*)(Clo + idx) = lp;
}

// ---------------------------------------------------------------------------
// Conversion kernels
// ---------------------------------------------------------------------------
__global__ void convert_x_kernel(const float* __restrict__ x) {
    int i4 = blockIdx.x * 256 + threadIdx.x;
    float4 v = ((const float4*)x)[i4];
    size_t b = (size_t)i4 * 4;
    split1(v.x, &g_xhi[b + 0], &g_xlo[b + 0]);
    split1(v.y, &g_xhi[b + 1], &g_xlo[b + 1]);
    split1(v.z, &g_xhi[b + 2], &g_xlo[b + 2]);
    split1(v.w, &g_xhi[b + 3], &g_xlo[b + 3]);
}

__global__ void convert_w_kernel(const float* __restrict__ Wq,
                                 const float* __restrict__ Wk,
                                 const float* __restrict__ Wv,
                                 const float* __restrict__ Wo) {
    int i4 = blockIdx.x * 256 + threadIdx.x;
    int per = WELEMS / 4;
    int mat = i4 / per;
    int off = i4 - mat * per;
    const float* src = (mat == 0) ? Wq : (mat == 1) ? Wk : (mat == 2) ? Wv : Wo;
    float4 v = ((const float4*)src)[off];
    size_t b = (size_t)mat * WELEMS + (size_t)off * 4;
    split1(v.x, &g_whi[b + 0], &g_wlo[b + 0]);
    split1(v.y, &g_whi[b + 1], &g_wlo[b + 1]);
    split1(v.z, &g_whi[b + 2], &g_wlo[b + 2]);
    split1(v.w, &g_whi[b + 3], &g_wlo[b + 3]);
}

// ---------------------------------------------------------------------------
// Split-bf16 GEMM via mma.sync (C = A @ W^T + bias), 128x128 tiles.
// Register-dieted mainloop: all B frags resident (32 regs), A frags streamed
// one mf at a time (8 regs) -> ~120 live regs -> 2 CTAs/SM.
// ---------------------------------------------------------------------------
#define GEMM_SMEM_BYTES (4 * 16384)

template <bool SPLIT>
__device__ __forceinline__ void gemm_tc_body(const __nv_bfloat16* __restrict__ Ahi,
                                             const __nv_bfloat16* __restrict__ Alo,
                                             const __nv_bfloat16* __restrict__ Whi,
                                             const __nv_bfloat16* __restrict__ Wlo,
                                             const float* __restrict__ bias,
                                             float* __restrict__ Cf,
                                             __nv_bfloat16* __restrict__ Chi,
                                             __nv_bfloat16* __restrict__ Clo,
                                             float scale)
{
    extern __shared__ char smem[];
    char* sAhi = smem;
    char* sWhi = smem + 32768;

    const int tid  = threadIdx.x;
    const int wid  = tid >> 5;
    const int lane = tid & 31;
    const int m0 = blockIdx.y * 128;
    const int n0 = blockIdx.x * 128;
    const int mBase = (wid >> 2) * 64;
    const int nBase = (wid & 3) * 32;

    const uint32_t xork = (lane & 7) * 16;
    const uint32_t aRow = smem_u32(sAhi) + (uint32_t)(mBase + (lane & 15)) * 128;
    const uint32_t aCol = ((lane >> 4) & 1) * 16;
    const uint32_t bRow = smem_u32(sWhi) + (uint32_t)(nBase + ((lane >> 4) << 3) + (lane & 7)) * 128;
    const uint32_t bCol = ((lane >> 3) & 1) * 16;

    const int cr = tid >> 1;
    const int ch = tid & 1;

    const __nv_bfloat16* gAh = Ahi + (size_t)(m0 + cr) * DIMD + ch * 32;
    const __nv_bfloat16* gAl = Alo + (size_t)(m0 + cr) * DIMD + ch * 32;
    const __nv_bfloat16* gWh = Whi + (size_t)(n0 + cr) * DIMD + ch * 32;
    const __nv_bfloat16* gWl = Wlo + (size_t)(n0 + cr) * DIMD + ch * 32;

    float c[4][4][4];
#pragma unroll
    for (int i = 0; i < 4; i++)
#pragma unroll
        for (int j = 0; j < 4; j++)
#pragma unroll
            for (int e = 0; e < 4; e++) c[i][j][e] = 0.f;

#pragma unroll 1
    for (int kc = 0; kc < DIMD / 64; ++kc) {
        __syncthreads();
#pragma unroll
        for (int i = 0; i < 4; ++i) {
            uint32_t off = (uint32_t)cr * 128 + ch * 64 + i * 16;
            uint32_t sw  = off ^ ((off >> 3) & 0x70);
            const int e  = i * 8;
            *(uint4*)(sAhi + sw) = *(const uint4*)(gAh + kc * 64 + e);
            *(uint4*)(sAhi + 16384 + sw) = *(const uint4*)(gAl + kc * 64 + e);
            *(uint4*)(sWhi + sw) = *(const uint4*)(gWh + kc * 64 + e);
            *(uint4*)(sWhi + 16384 + sw) = *(const uint4*)(gWl + kc * 64 + e);
        }
        __syncthreads();

#pragma unroll
        for (int ks = 0; ks < 4; ++ks) {
            const uint32_t ca = ((uint32_t)(ks * 32) + aCol) ^ xork;
            const uint32_t cb = ((uint32_t)(ks * 32) + bCol) ^ xork;

            // all B fragments resident for this k-step (32 regs)
            uint32_t bhi[2][4], blo[2][4];
#pragma unroll
            for (int nh = 0; nh < 2; ++nh) {
                ldm_x4(bhi[nh], bRow + nh * 2048 + cb);
                ldm_x4(blo[nh], bRow + 16384u + nh * 2048 + cb);
            }

            // stream A fragments one mf at a time (8 live regs)
#pragma unroll
            for (int mf = 0; mf < 4; ++mf) {
                uint32_t ahi[4], alo[4];
                ldm_x4(ahi, aRow + mf * 2048 + ca);
                ldm_x4(alo, aRow + 16384u + mf * 2048 + ca);
#pragma unroll
                for (int nf = 0; nf < 4; ++nf) {
                    const uint32_t* bh = &bhi[nf >> 1][(nf & 1) * 2];
                    const uint32_t* bl = &blo[nf >> 1][(nf & 1) * 2];
                    mma16816(c[mf][nf], ahi, bh);
                    mma16816(c[mf][nf], ahi, bl);
                    mma16816(c[mf][nf], alo, bh);
                }
            }
        }
    }

    const int rA = m0 + mBase + (lane >> 2);
    const int cA = n0 + nBase + (lane & 3) * 2;
#pragma unroll
    for (int mf = 0; mf < 4; ++mf)
#pragma unroll
        for (int nf = 0; nf < 4; ++nf) {
            const int row = rA + mf * 16;
            const int col = cA + nf * 8;
            const float b0 = bias[col], b1 = bias[col + 1];
            float v00 = c[mf][nf][0] + b0, v01 = c[mf][nf][1] + b1;
            float v10 = c[mf][nf][2] + b0, v11 = c[mf][nf][3] + b1;
            if (SPLIT) {
                v00 *= scale; v01 *= scale; v10 *= scale; v11 *= scale;
                store_split2(Chi, Clo, (size_t)row * DIMD + col, v00, v01);
                store_split2(Chi, Clo, (size_t)(row + 8) * DIMD + col, v10, v11);
            } else {
                *(float2*)(Cf + (size_t)row * DIMD + col) = make_float2(v00, v01);
                *(float2*)(Cf + (size_t)(row + 8) * DIMD + col) = make_float2(v10, v11);
            }
        }
}

__global__ void __launch_bounds__(256, 2)
qkv_tc_kernel(const float* __restrict__ bq, const float* __restrict__ bk,
              const float* __restrict__ bv)
{
    const int z = blockIdx.z;
    const float* bias = (z == 0) ? bq : (z == 1) ? bk : bv;
    __nv_bfloat16* Chi = (z == 0) ? g_qhi : (z == 1) ? g_khi : g_vhi;
    __nv_bfloat16* Clo = (z == 0) ? g_qlo : (z == 1) ? g_klo : g_vlo;
    const float scale = (z == 0) ? SQRT48 * LOG2E : 1.0f;   // fold log2e -> exp2
    gemm_tc_body<true>(g_xhi, g_xlo, g_whi + (size_t)z * WELEMS,
                       g_wlo + (size_t)z * WELEMS, bias, nullptr, Chi, Clo, scale);
}

__global__ void __launch_bounds__(256, 2)
proj_tc_kernel(const float* __restrict__ bo, float* __restrict__ out)
{
    gemm_tc_body<false>(g_ahi, g_alo, g_whi + 3ULL * WELEMS, g_wlo + 3ULL * WELEMS,
                        bo, out, nullptr, nullptr, 1.0f);
}

// ---------------------------------------------------------------------------
// FlashAttention-2 via mma.sync, split-bf16, 64-col inner chunks.
// Register diet (<=128) -> 2 CTAs/SM. Logits are base-2 (log2e pre-folded).
// ---------------------------------------------------------------------------
#define ATS 112                     // bytes per padded tile row (56 bf16)
#define ATILE_BYTES (128 * ATS)     // 14336
#define ATTN_SMEM_BYTES (6 * ATILE_BYTES)

__global__ void __launch_bounds__(256, 2)
attn_tc_kernel()
{
    extern __shared__ char smem[];

    const int tid  = threadIdx.x;
    const int wid  = tid >> 5;
    const int lane = tid & 31;
    const int bid  = blockIdx.x;
    const int qt   = bid & 15;
    const size_t slab = (size_t)(bid >> 4) * (SEQ * HD);
    const int q0   = qt * 128;

    const uint32_t sbase = smem_u32(smem);
    const uint32_t qOff = (uint32_t)((wid * 16 + (lane & 15)) * ATS + ((lane >> 4) & 1) * 16);
    const uint32_t kOff = (uint32_t)(((((lane >> 4) & 1) << 3) + (lane & 7)) * ATS + ((lane >> 3) & 1) * 16);
    const uint32_t vOff = (uint32_t)(((lane & 7) + ((lane >> 3) & 1) * 8) * ATS + ((lane >> 4) & 1) * 16);

    // ---- load Q tile (once)
    {
        const uint4* gh = (const uint4*)(g_qhi + slab + (size_t)q0 * HD);
        const uint4* gl = (const uint4*)(g_qlo + slab + (size_t)q0 * HD);
#pragma unroll
        for (int u = 0; u < 3; ++u) {
            int gi = tid + u * 256;
            int r = gi / 6, j = gi - r * 6;
            int so = r * ATS + j * 16;
            *(uint4*)(smem + so) = gh[gi];
            *(uint4*)(smem + ATILE_BYTES + so) = gl[gi];
        }
    }

    float o[6][4];
#pragma unroll
    for (int i = 0; i < 6; i++)
#pragma unroll
        for (int e = 0; e < 4; e++) o[i][e] = 0.f;
    float m0r = -INFINITY, m1r = -INFINITY, l0 = 0.f, l1 = 0.f;

#pragma unroll 1
    for (int t = 0; t < SEQ / 128; ++t) {
        __syncthreads();
        {
            const size_t tb = slab + (size_t)(t * 128) * HD;
            const uint4* kh = (const uint4*)(g_khi + tb);
            const uint4* kl = (const uint4*)(g_klo + tb);
            const uint4* vh = (const uint4*)(g_vhi + tb);
            const uint4* vl = (const uint4*)(g_vlo + tb);
#pragma unroll
            for (int u = 0; u < 3; ++u) {
                int gi = tid + u * 256;
                int r = gi / 6, j = gi - r * 6;
                int so = r * ATS + j * 16;
                *(uint4*)(smem + 2 * ATILE_BYTES + so) = kh[gi];
                *(uint4*)(smem + 3 * ATILE_BYTES + so) = kl[gi];
                *(uint4*)(smem + 4 * ATILE_BYTES + so) = vh[gi];
                *(uint4*)(smem + 5 * ATILE_BYTES + so) = vl[gi];
            }
        }
        __syncthreads();

#pragma unroll 1
        for (int h = 0; h < 2; ++h) {
            // ---- S chunk: 16 q-rows x 64 k-cols, 3-product split
            float c[8][4];
#pragma unroll
            for (int i = 0; i < 8; i++)
#pragma unroll
                for (int e = 0; e < 4; e++) c[i][e] = 0.f;

#pragma unroll
            for (int ks = 0; ks < 3; ++ks) {
                uint32_t qh[4], ql[4];
                ldm_x4(qh, sbase + qOff + ks * 32);
                ldm_x4(ql, sbase + ATILE_BYTES + qOff + ks * 32);
#pragma unroll
                for (int ng = 0; ng < 4; ++ng) {
                    uint32_t kh4[4], kl4[4];
                    const uint32_t ka = sbase + 2 * ATILE_BYTES + kOff
                                      + (uint32_t)(h * 64 + ng * 16) * ATS + ks * 32;
                    ldm_x4(kh4, ka);
                    ldm_x4(kl4, ka + ATILE_BYTES);
                    mma16816(c[2 * ng],     qh, kh4);
                    mma16816(c[2 * ng],     qh, kl4);
                    mma16816(c[2 * ng],     ql, kh4);
                    mma16816(c[2 * ng + 1], qh, kh4 + 2);
                    mma16816(c[2 * ng + 1], qh, kl4 + 2);
                    mma16816(c[2 * ng + 1], ql, kh4 + 2);
                }
            }

            // ---- online softmax over this 64-col chunk (base-2 logits)
            float mt0 = c[0][0], mt1 = c[0][2];
#pragma unroll
            for (int nf = 0; nf < 8; ++nf) {
                mt0 = fmaxf(mt0, fmaxf(c[nf][0], c[nf][1]));
                mt1 = fmaxf(mt1, fmaxf(c[nf][2], c[nf][3]));
            }
            mt0 = fmaxf(mt0, __shfl_xor_sync(0xffffffffu, mt0, 1));
            mt0 = fmaxf(mt0, __shfl_xor_sync(0xffffffffu, mt0, 2));
            mt1 = fmaxf(mt1, __shfl_xor_sync(0xffffffffu, mt1, 1));
            mt1 = fmaxf(mt1, __shfl_xor_sync(0xffffffffu, mt1, 2));

            const float mn0 = fmaxf(m0r, mt0), mn1 = fmaxf(m1r, mt1);
            const float f0 = exp2f(m0r - mn0), f1 = exp2f(m1r - mn1);
            m0r = mn0; m1r = mn1;

            float rs0 = 0.f, rs1 = 0.f;
            uint32_t pH[8][2], pL[8][2];
#pragma unroll
            for (int nf = 0; nf < 8; ++nf) {
                float p0 = exp2f(c[nf][0] - mn0);
                float p1 = exp2f(c[nf][1] - mn0);
                float p2 = exp2f(c[nf][2] - mn1);
                float p3 = exp2f(c[nf][3] - mn1);
                rs0 += p0 + p1; rs1 += p2 + p3;
                __nv_bfloat16 h0 = __float2bfloat16(p0), h1 = __float2bfloat16(p1);
                __nv_bfloat16 h2 = __float2bfloat16(p2), h3 = __float2bfloat16(p3);
                pH[nf][0] = pack2(h0, h1);
                pH[nf][1] = pack2(h2, h3);
                pL[nf][0] = pack2(__float2bfloat16(p0 - __bfloat162float(h0)),
                                  __float2bfloat16(p1 - __bfloat162float(h1)));
                pL[nf][1] = pack2(__float2bfloat16(p2 - __bfloat162float(h2)),
                                  __float2bfloat16(p3 - __bfloat162float(h3)));
            }
            rs0 += __shfl_xor_sync(0xffffffffu, rs0, 1);
            rs0 += __shfl_xor_sync(0xffffffffu, rs0, 2);
            rs1 += __shfl_xor_sync(0xffffffffu, rs1, 1);
            rs1 += __shfl_xor_sync(0xffffffffu, rs1, 2);
            l0 = l0 * f0 + rs0;
            l1 = l1 * f1 + rs1;

#pragma unroll
            for (int nc = 0; nc < 6; ++nc) {
                o[nc][0] *= f0; o[nc][1] *= f0;
                o[nc][2] *= f1; o[nc][3] *= f1;
            }

            // ---- O += P V over this 64-row V chunk
#pragma unroll
            for (int kk = 0; kk < 4; ++kk) {
                uint32_t aH[4] = {pH[2 * kk][0], pH[2 * kk][1],
                                  pH[2 * kk + 1][0], pH[2 * kk + 1][1]};
                uint32_t aL[4] = {pL[2 * kk][0], pL[2 * kk][1],
                                  pL[2 * kk + 1][0], pL[2 * kk + 1][1]};
#pragma unroll
                for (int nc = 0; nc < 3; ++nc) {
                    uint32_t vh4[4], vl4[4];
                    const uint32_t va = sbase + 4 * ATILE_BYTES + vOff
                                      + (uint32_t)(h * 64 + kk * 16) * ATS + nc * 32;
                    ldm_x4_t(vh4, va);
                    ldm_x4_t(vl4, va + ATILE_BYTES);
                    mma16816(o[2 * nc],     aH, vh4);
                    mma16816(o[2 * nc],     aH, vl4);
                    mma16816(o[2 * nc],     aL, vh4);
                    mma16816(o[2 * nc + 1], aH, vh4 + 2);
                    mma16816(o[2 * nc + 1], aH, vl4 + 2);
                    mma16816(o[2 * nc + 1], aL, vh4 + 2);
                }
            }
        }
    }

    // ---- finalize: /l, split-store to g_ahi/g_alo (raw-view layout)
    const float inv0 = 1.f / l0, inv1 = 1.f / l1;
    const int r0 = q0 + wid * 16 + (lane >> 2);
    const int cc = (lane & 3) * 2;
#pragma unroll
    for (int nf = 0; nf < 6; ++nf) {
        const int col = nf * 8 + cc;
        store_split2(g_ahi, g_alo, slab + (size_t)r0 * HD + col,
                     o[nf][0] * inv0, o[nf][1] * inv0);
        store_split2(g_ahi, g_alo, slab + (size_t)(r0 + 8) * HD + col,
                     o[nf][2] * inv1, o[nf][3] * inv1);
    }
}

// ---------------------------------------------------------------------------
extern "C" void kernel_launch(void* const* d_in, const int* in_sizes, int n_in,
                              void* d_out, int out_size)
{
    const float* x  = (const float*)d_in[0];
    const float* Wq = (const float*)d_in[1];
    const float* bq = (const float*)d_in[2];
    const float* Wk = (const float*)d_in[3];
    const float* bk = (const float*)d_in[4];
    const float* Wv = (const float*)d_in[5];
    const float* bv = (const float*)d_in[6];
    const float* Wo = (const float*)d_in[7];
    const float* bo = (const float*)d_in[8];
    float* out = (float*)d_out;

    cudaFuncSetAttribute(attn_tc_kernel, cudaFuncAttributeMaxDynamicSharedMemorySize,
                         ATTN_SMEM_BYTES);
    cudaFuncSetAttribute(qkv_tc_kernel, cudaFuncAttributeMaxDynamicSharedMemorySize,
                         GEMM_SMEM_BYTES);
    cudaFuncSetAttribute(proj_tc_kernel, cudaFuncAttributeMaxDynamicSharedMemorySize,
                         GEMM_SMEM_BYTES);

    convert_w_kernel<<<4 * WELEMS / 4 / 256, 256>>>(Wq, Wk, Wv, Wo);
    convert_x_kernel<<<MROWS * DIMD / 4 / 256, 256>>>(x);

    dim3 gqkv(DIMD / 128, MROWS / 128, 3);
    qkv_tc_kernel<<<gqkv, 256, GEMM_SMEM_BYTES>>>(bq, bk, bv);

    attn_tc_kernel<<<(MROWS / 128) * NHEADS, 256, ATTN_SMEM_BYTES>>>();

    dim3 gproj(DIMD / 128, MROWS / 128);
    proj_tc_kernel<<<gproj, 256, GEMM_SMEM_BYTES>>>(bo, out);

    (void)in_sizes; (void)n_in; (void)out_size;
}

// round 10
// speedup vs baseline: 2.7162x; 1.0017x over previous
#include <cuda_runtime.h>
#include <cuda_bf16.h>
#include <math.h>
#include <stdint.h>

// Problem constants
#define DIMD   768
#define MROWS  8192          // B*N = 4*2048
#define NHEADS 16
#define HD     48
#define SEQ    2048
#define SQRT48 6.9282032302755091741f
#define LOG2E  1.4426950408889634074f
#define WELEMS (DIMD * DIMD)

// ---------------------------------------------------------------------------
// Scratch (__device__ globals; no allocations anywhere)
// ---------------------------------------------------------------------------
__device__ __nv_bfloat16 g_xhi[MROWS * DIMD];
__device__ __nv_bfloat16 g_xlo[MROWS * DIMD];
__device__ __nv_bfloat16 g_qhi[MROWS * DIMD];   // pre-scaled by sqrt(48)*log2e
__device__ __nv_bfloat16 g_qlo[MROWS * DIMD];
__device__ __nv_bfloat16 g_khi[MROWS * DIMD];
__device__ __nv_bfloat16 g_klo[MROWS * DIMD];
__device__ __nv_bfloat16 g_vhi[MROWS * DIMD];
__device__ __nv_bfloat16 g_vlo[MROWS * DIMD];
__device__ __nv_bfloat16 g_ahi[MROWS * DIMD];
__device__ __nv_bfloat16 g_alo[MROWS * DIMD];
__device__ __nv_bfloat16 g_whi[4 * WELEMS];
__device__ __nv_bfloat16 g_wlo[4 * WELEMS];

// ---------------------------------------------------------------------------
// mma.sync helpers (baseline PTX — legal on plain sm_100 target)
// ---------------------------------------------------------------------------
__device__ __forceinline__ uint32_t smem_u32(const void* p) {
    uint32_t a;
    asm("{ .reg .u64 t; cvta.to.shared.u64 t, %1; cvt.u32.u64 %0, t; }"
        : "=r"(a) : "l"(p));
    return a;
}

__device__ __forceinline__ void ldm_x4(uint32_t* r, uint32_t addr) {
    asm volatile("ldmatrix.sync.aligned.m8n8.x4.shared.b16 {%0,%1,%2,%3}, [%4];"
                 : "=r"(r[0]), "=r"(r[1]), "=r"(r[2]), "=r"(r[3]) : "r"(addr));
}

__device__ __forceinline__ void ldm_x4_t(uint32_t* r, uint32_t addr) {
    asm volatile("ldmatrix.sync.aligned.m8n8.x4.trans.shared.b16 {%0,%1,%2,%3}, [%4];"
                 : "=r"(r[0]), "=r"(r[1]), "=r"(r[2]), "=r"(r[3]) : "r"(addr));
}

__device__ __forceinline__ void mma16816(float* c, const uint32_t* a,
                                         const uint32_t* b) {
    asm volatile(
        "mma.sync.aligned.m16n8k16.row.col.f32.bf16.bf16.f32 "
        "{%0,%1,%2,%3}, {%4,%5,%6,%7}, {%8,%9}, {%0,%1,%2,%3};"
        : "+f"(c[0]), "+f"(c[1]), "+f"(c[2]), "+f"(c[3])
        : "r"(a[0]), "r"(a[1]), "r"(a[2]), "r"(a[3]), "r"(b[0]), "r"(b[1]));
}

__device__ __forceinline__ uint32_t pack2(__nv_bfloat16 a, __nv_bfloat16 b) {
    __nv_bfloat162 t; t.x = a; t.y = b;
    return *(uint32_t*)&t;
}

__device__ __forceinline__ void split1(float v, __nv_bfloat16* hi, __nv_bfloat16* lo) {
    __nv_bfloat16 h = __float2bfloat16(v);
    *hi = h;
    *lo = __float2bfloat16(v - __bfloat162float(h));
}

__device__ __forceinline__ void store_split2(__nv_bfloat16* Chi, __nv_bfloat16* Clo,
                                             size_t idx, float a, float b) {
    __nv_bfloat16 ha = __float2bfloat16(a), hb = __float2bfloat16(b);
    __nv_bfloat162 hp; hp.x = ha; hp.y = hb;
    *(__nv_bfloat162*)(Chi + idx) = hp;
    __nv_bfloat162 lp;
    lp.x = __float2bfloat16(a - __bfloat162float(ha));
    lp.y = __float2bfloat16(b - __bfloat162float(hb));
    *(__nv_bfloat162*)(Clo + idx) = lp;
}

// ---------------------------------------------------------------------------
// Conversion kernels
// ---------------------------------------------------------------------------
__global__ void convert_x_kernel(const float* __restrict__ x) {
    int i4 = blockIdx.x * 256 + threadIdx.x;
    float4 v = ((const float4*)x)[i4];
    size_t b = (size_t)i4 * 4;
    split1(v.x, &g_xhi[b + 0], &g_xlo[b + 0]);
    split1(v.y, &g_xhi[b + 1], &g_xlo[b + 1]);
    split1(v.z, &g_xhi[b + 2], &g_xlo[b + 2]);
    split1(v.w, &g_xhi[b + 3], &g_xlo[b + 3]);
}

__global__ void convert_w_kernel(const float* __restrict__ Wq,
                                 const float* __restrict__ Wk,
                                 const float* __restrict__ Wv,
                                 const float* __restrict__ Wo) {
    int i4 = blockIdx.x * 256 + threadIdx.x;
    int per = WELEMS / 4;
    int mat = i4 / per;
    int off = i4 - mat * per;
    const float* src = (mat == 0) ? Wq : (mat == 1) ? Wk : (mat == 2) ? Wv : Wo;
    float4 v = ((const float4*)src)[off];
    size_t b = (size_t)mat * WELEMS + (size_t)off * 4;
    split1(v.x, &g_whi[b + 0], &g_wlo[b + 0]);
    split1(v.y, &g_whi[b + 1], &g_wlo[b + 1]);
    split1(v.z, &g_whi[b + 2], &g_wlo[b + 2]);
    split1(v.w, &g_whi[b + 3], &g_wlo[b + 3]);
}

// ---------------------------------------------------------------------------
// Split-bf16 GEMM via mma.sync (C = A @ W^T + bias), 128x128 tiles.
// Product-major mma ordering: accumulator reuse distance 4 (RAW hiding).
// ---------------------------------------------------------------------------
#define GEMM_SMEM_BYTES (4 * 16384)

template <bool SPLIT>
__device__ __forceinline__ void gemm_tc_body(const __nv_bfloat16* __restrict__ Ahi,
                                             const __nv_bfloat16* __restrict__ Alo,
                                             const __nv_bfloat16* __restrict__ Whi,
                                             const __nv_bfloat16* __restrict__ Wlo,
                                             const float* __restrict__ bias,
                                             float* __restrict__ Cf,
                                             __nv_bfloat16* __restrict__ Chi,
                                             __nv_bfloat16* __restrict__ Clo,
                                             float scale)
{
    extern __shared__ char smem[];
    char* sAhi = smem;
    char* sWhi = smem + 32768;

    const int tid  = threadIdx.x;
    const int wid  = tid >> 5;
    const int lane = tid & 31;
    const int m0 = blockIdx.y * 128;
    const int n0 = blockIdx.x * 128;
    const int mBase = (wid >> 2) * 64;
    const int nBase = (wid & 3) * 32;

    const uint32_t xork = (lane & 7) * 16;
    const uint32_t aRow = smem_u32(sAhi) + (uint32_t)(mBase + (lane & 15)) * 128;
    const uint32_t aCol = ((lane >> 4) & 1) * 16;
    const uint32_t bRow = smem_u32(sWhi) + (uint32_t)(nBase + ((lane >> 4) << 3) + (lane & 7)) * 128;
    const uint32_t bCol = ((lane >> 3) & 1) * 16;

    const int cr = tid >> 1;
    const int ch = tid & 1;

    const __nv_bfloat16* gAh = Ahi + (size_t)(m0 + cr) * DIMD + ch * 32;
    const __nv_bfloat16* gAl = Alo + (size_t)(m0 + cr) * DIMD + ch * 32;
    const __nv_bfloat16* gWh = Whi + (size_t)(n0 + cr) * DIMD + ch * 32;
    const __nv_bfloat16* gWl = Wlo + (size_t)(n0 + cr) * DIMD + ch * 32;

    float c[4][4][4];
#pragma unroll
    for (int i = 0; i < 4; i++)
#pragma unroll
        for (int j = 0; j < 4; j++)
#pragma unroll
            for (int e = 0; e < 4; e++) c[i][j][e] = 0.f;

#pragma unroll 1
    for (int kc = 0; kc < DIMD / 64; ++kc) {
        __syncthreads();
#pragma unroll
        for (int i = 0; i < 4; ++i) {
            uint32_t off = (uint32_t)cr * 128 + ch * 64 + i * 16;
            uint32_t sw  = off ^ ((off >> 3) & 0x70);
            const int e  = i * 8;
            *(uint4*)(sAhi + sw) = *(const uint4*)(gAh + kc * 64 + e);
            *(uint4*)(sAhi + 16384 + sw) = *(const uint4*)(gAl + kc * 64 + e);
            *(uint4*)(sWhi + sw) = *(const uint4*)(gWh + kc * 64 + e);
            *(uint4*)(sWhi + 16384 + sw) = *(const uint4*)(gWl + kc * 64 + e);
        }
        __syncthreads();

#pragma unroll
        for (int ks = 0; ks < 4; ++ks) {
            const uint32_t ca = ((uint32_t)(ks * 32) + aCol) ^ xork;
            const uint32_t cb = ((uint32_t)(ks * 32) + bCol) ^ xork;

            // all B fragments resident for this k-step (32 regs)
            uint32_t bhi[2][4], blo[2][4];
#pragma unroll
            for (int nh = 0; nh < 2; ++nh) {
                ldm_x4(bhi[nh], bRow + nh * 2048 + cb);
                ldm_x4(blo[nh], bRow + 16384u + nh * 2048 + cb);
            }

            // stream A fragments one mf at a time; product-major over nf
            // => same-accumulator reuse distance 4 (hides mma RAW latency)
#pragma unroll
            for (int mf = 0; mf < 4; ++mf) {
                uint32_t ahi[4], alo[4];
                ldm_x4(ahi, aRow + mf * 2048 + ca);
                ldm_x4(alo, aRow + 16384u + mf * 2048 + ca);
#pragma unroll
                for (int nf = 0; nf < 4; ++nf)
                    mma16816(c[mf][nf], ahi, &bhi[nf >> 1][(nf & 1) * 2]);
#pragma unroll
                for (int nf = 0; nf < 4; ++nf)
                    mma16816(c[mf][nf], ahi, &blo[nf >> 1][(nf & 1) * 2]);
#pragma unroll
                for (int nf = 0; nf < 4; ++nf)
                    mma16816(c[mf][nf], alo, &bhi[nf >> 1][(nf & 1) * 2]);
            }
        }
    }

    const int rA = m0 + mBase + (lane >> 2);
    const int cA = n0 + nBase + (lane & 3) * 2;
#pragma unroll
    for (int mf = 0; mf < 4; ++mf)
#pragma unroll
        for (int nf = 0; nf < 4; ++nf) {
            const int row = rA + mf * 16;
            const int col = cA + nf * 8;
            const float b0 = bias[col], b1 = bias[col + 1];
            float v00 = c[mf][nf][0] + b0, v01 = c[mf][nf][1] + b1;
            float v10 = c[mf][nf][2] + b0, v11 = c[mf][nf][3] + b1;
            if (SPLIT) {
                v00 *= scale; v01 *= scale; v10 *= scale; v11 *= scale;
                store_split2(Chi, Clo, (size_t)row * DIMD + col, v00, v01);
                store_split2(Chi, Clo, (size_t)(row + 8) * DIMD + col, v10, v11);
            } else {
                *(float2*)(Cf + (size_t)row * DIMD + col) = make_float2(v00, v01);
                *(float2*)(Cf + (size_t)(row + 8) * DIMD + col) = make_float2(v10, v11);
            }
        }
}

__global__ void __launch_bounds__(256, 2)
qkv_tc_kernel(const float* __restrict__ bq, const float* __restrict__ bk,
              const float* __restrict__ bv)
{
    const int z = blockIdx.z;
    const float* bias = (z == 0) ? bq : (z == 1) ? bk : bv;
    __nv_bfloat16* Chi = (z == 0) ? g_qhi : (z == 1) ? g_khi : g_vhi;
    __nv_bfloat16* Clo = (z == 0) ? g_qlo : (z == 1) ? g_klo : g_vlo;
    const float scale = (z == 0) ? SQRT48 * LOG2E : 1.0f;   // fold log2e -> exp2
    gemm_tc_body<true>(g_xhi, g_xlo, g_whi + (size_t)z * WELEMS,
                       g_wlo + (size_t)z * WELEMS, bias, nullptr, Chi, Clo, scale);
}

__global__ void __launch_bounds__(256, 2)
proj_tc_kernel(const float* __restrict__ bo, float* __restrict__ out)
{
    gemm_tc_body<false>(g_ahi, g_alo, g_whi + 3ULL * WELEMS, g_wlo + 3ULL * WELEMS,
                        bo, out, nullptr, nullptr, 1.0f);
}

// ---------------------------------------------------------------------------
// FlashAttention-2 via mma.sync, split-bf16, 64-col inner chunks.
// 2 CTAs/SM; product-major mma scheduling for accumulator RAW hiding.
// ---------------------------------------------------------------------------
#define ATS 112                     // bytes per padded tile row (56 bf16)
#define ATILE_BYTES (128 * ATS)     // 14336
#define ATTN_SMEM_BYTES (6 * ATILE_BYTES)

__global__ void __launch_bounds__(256, 2)
attn_tc_kernel()
{
    extern __shared__ char smem[];

    const int tid  = threadIdx.x;
    const int wid  = tid >> 5;
    const int lane = tid & 31;
    const int bid  = blockIdx.x;
    const int qt   = bid & 15;
    const size_t slab = (size_t)(bid >> 4) * (SEQ * HD);
    const int q0   = qt * 128;

    const uint32_t sbase = smem_u32(smem);
    const uint32_t qOff = (uint32_t)((wid * 16 + (lane & 15)) * ATS + ((lane >> 4) & 1) * 16);
    const uint32_t kOff = (uint32_t)(((((lane >> 4) & 1) << 3) + (lane & 7)) * ATS + ((lane >> 3) & 1) * 16);
    const uint32_t vOff = (uint32_t)(((lane & 7) + ((lane >> 3) & 1) * 8) * ATS + ((lane >> 4) & 1) * 16);

    // ---- load Q tile (once)
    {
        const uint4* gh = (const uint4*)(g_qhi + slab + (size_t)q0 * HD);
        const uint4* gl = (const uint4*)(g_qlo + slab + (size_t)q0 * HD);
#pragma unroll
        for (int u = 0; u < 3; ++u) {
            int gi = tid + u * 256;
            int r = gi / 6, j = gi - r * 6;
            int so = r * ATS + j * 16;
            *(uint4*)(smem + so) = gh[gi];
            *(uint4*)(smem + ATILE_BYTES + so) = gl[gi];
        }
    }

    float o[6][4];
#pragma unroll
    for (int i = 0; i < 6; i++)
#pragma unroll
        for (int e = 0; e < 4; e++) o[i][e] = 0.f;
    float m0r = -INFINITY, m1r = -INFINITY, l0 = 0.f, l1 = 0.f;

#pragma unroll 1
    for (int t = 0; t < SEQ / 128; ++t) {
        __syncthreads();
        {
            const size_t tb = slab + (size_t)(t * 128) * HD;
            const uint4* kh = (const uint4*)(g_khi + tb);
            const uint4* kl = (const uint4*)(g_klo + tb);
            const uint4* vh = (const uint4*)(g_vhi + tb);
            const uint4* vl = (const uint4*)(g_vlo + tb);
#pragma unroll
            for (int u = 0; u < 3; ++u) {
                int gi = tid + u * 256;
                int r = gi / 6, j = gi - r * 6;
                int so = r * ATS + j * 16;
                *(uint4*)(smem + 2 * ATILE_BYTES + so) = kh[gi];
                *(uint4*)(smem + 3 * ATILE_BYTES + so) = kl[gi];
                *(uint4*)(smem + 4 * ATILE_BYTES + so) = vh[gi];
                *(uint4*)(smem + 5 * ATILE_BYTES + so) = vl[gi];
            }
        }
        __syncthreads();

#pragma unroll 1
        for (int h = 0; h < 2; ++h) {
            // ---- S chunk: 16 q-rows x 64 k-cols, 3-product split.
            // Two ng per pass, product-major over 4 accumulators (distance 4).
            float c[8][4];
#pragma unroll
            for (int i = 0; i < 8; i++)
#pragma unroll
                for (int e = 0; e < 4; e++) c[i][e] = 0.f;

#pragma unroll
            for (int ks = 0; ks < 3; ++ks) {
                uint32_t qh[4], ql[4];
                ldm_x4(qh, sbase + qOff + ks * 32);
                ldm_x4(ql, sbase + ATILE_BYTES + qOff + ks * 32);
#pragma unroll
                for (int np = 0; np < 2; ++np) {
                    uint32_t kh4[2][4], kl4[2][4];
#pragma unroll
                    for (int g = 0; g < 2; ++g) {
                        const uint32_t ka = sbase + 2 * ATILE_BYTES + kOff
                                          + (uint32_t)(h * 64 + (np * 2 + g) * 16) * ATS + ks * 32;
                        ldm_x4(kh4[g], ka);
                        ldm_x4(kl4[g], ka + ATILE_BYTES);
                    }
                    float* cc = &c[4 * np][0];
                    // hh pass
                    mma16816(cc + 0,  qh, kh4[0]);
                    mma16816(cc + 4,  qh, kh4[0] + 2);
                    mma16816(cc + 8,  qh, kh4[1]);
                    mma16816(cc + 12, qh, kh4[1] + 2);
                    // hl pass
                    mma16816(cc + 0,  qh, kl4[0]);
                    mma16816(cc + 4,  qh, kl4[0] + 2);
                    mma16816(cc + 8,  qh, kl4[1]);
                    mma16816(cc + 12, qh, kl4[1] + 2);
                    // lh pass
                    mma16816(cc + 0,  ql, kh4[0]);
                    mma16816(cc + 4,  ql, kh4[0] + 2);
                    mma16816(cc + 8,  ql, kh4[1]);
                    mma16816(cc + 12, ql, kh4[1] + 2);
                }
            }

            // ---- online softmax over this 64-col chunk (base-2 logits)
            float mt0 = c[0][0], mt1 = c[0][2];
#pragma unroll
            for (int nf = 0; nf < 8; ++nf) {
                mt0 = fmaxf(mt0, fmaxf(c[nf][0], c[nf][1]));
                mt1 = fmaxf(mt1, fmaxf(c[nf][2], c[nf][3]));
            }
            mt0 = fmaxf(mt0, __shfl_xor_sync(0xffffffffu, mt0, 1));
            mt0 = fmaxf(mt0, __shfl_xor_sync(0xffffffffu, mt0, 2));
            mt1 = fmaxf(mt1, __shfl_xor_sync(0xffffffffu, mt1, 1));
            mt1 = fmaxf(mt1, __shfl_xor_sync(0xffffffffu, mt1, 2));

            const float mn0 = fmaxf(m0r, mt0), mn1 = fmaxf(m1r, mt1);
            const float f0 = exp2f(m0r - mn0), f1 = exp2f(m1r - mn1);
            m0r = mn0; m1r = mn1;

            float rs0 = 0.f, rs1 = 0.f;
            uint32_t pH[8][2], pL[8][2];
#pragma unroll
            for (int nf = 0; nf < 8; ++nf) {
                float p0 = exp2f(c[nf][0] - mn0);
                float p1 = exp2f(c[nf][1] - mn0);
                float p2 = exp2f(c[nf][2] - mn1);
                float p3 = exp2f(c[nf][3] - mn1);
                rs0 += p0 + p1; rs1 += p2 + p3;
                __nv_bfloat16 h0 = __float2bfloat16(p0), h1 = __float2bfloat16(p1);
                __nv_bfloat16 h2 = __float2bfloat16(p2), h3 = __float2bfloat16(p3);
                pH[nf][0] = pack2(h0, h1);
                pH[nf][1] = pack2(h2, h3);
                pL[nf][0] = pack2(__float2bfloat16(p0 - __bfloat162float(h0)),
                                  __float2bfloat16(p1 - __bfloat162float(h1)));
                pL[nf][1] = pack2(__float2bfloat16(p2 - __bfloat162float(h2)),
                                  __float2bfloat16(p3 - __bfloat162float(h3)));
            }
            rs0 += __shfl_xor_sync(0xffffffffu, rs0, 1);
            rs0 += __shfl_xor_sync(0xffffffffu, rs0, 2);
            rs1 += __shfl_xor_sync(0xffffffffu, rs1, 1);
            rs1 += __shfl_xor_sync(0xffffffffu, rs1, 2);
            l0 = l0 * f0 + rs0;
            l1 = l1 * f1 + rs1;

#pragma unroll
            for (int nc = 0; nc < 6; ++nc) {
                o[nc][0] *= f0; o[nc][1] *= f0;
                o[nc][2] *= f1; o[nc][3] *= f1;
            }

            // ---- O += P V over this 64-row V chunk
            // Interleave o[2nc]/o[2nc+1] per product (distance 2).
#pragma unroll
            for (int kk = 0; kk < 4; ++kk) {
                uint32_t aH[4] = {pH[2 * kk][0], pH[2 * kk][1],
                                  pH[2 * kk + 1][0], pH[2 * kk + 1][1]};
                uint32_t aL[4] = {pL[2 * kk][0], pL[2 * kk][1],
                                  pL[2 * kk + 1][0], pL[2 * kk + 1][1]};
#pragma unroll
                for (int nc = 0; nc < 3; ++nc) {
                    uint32_t vh4[4], vl4[4];
                    const uint32_t va = sbase + 4 * ATILE_BYTES + vOff
                                      + (uint32_t)(h * 64 + kk * 16) * ATS + nc * 32;
                    ldm_x4_t(vh4, va);
                    ldm_x4_t(vl4, va + ATILE_BYTES);
                    mma16816(o[2 * nc],     aH, vh4);
                    mma16816(o[2 * nc + 1], aH, vh4 + 2);
                    mma16816(o[2 * nc],     aH, vl4);
                    mma16816(o[2 * nc + 1], aH, vl4 + 2);
                    mma16816(o[2 * nc],     aL, vh4);
                    mma16816(o[2 * nc + 1], aL, vh4 + 2);
                }
            }
        }
    }

    // ---- finalize: /l, split-store to g_ahi/g_alo (raw-view layout)
    const float inv0 = 1.f / l0, inv1 = 1.f / l1;
    const int r0 = q0 + wid * 16 + (lane >> 2);
    const int cc = (lane & 3) * 2;
#pragma unroll
    for (int nf = 0; nf < 6; ++nf) {
        const int col = nf * 8 + cc;
        store_split2(g_ahi, g_alo, slab + (size_t)r0 * HD + col,
                     o[nf][0] * inv0, o[nf][1] * inv0);
        store_split2(g_ahi, g_alo, slab + (size_t)(r0 + 8) * HD + col,
                     o[nf][2] * inv1, o[nf][3] * inv1);
    }
}

// ---------------------------------------------------------------------------
extern "C" void kernel_launch(void* const* d_in, const int* in_sizes, int n_in,
                              void* d_out, int out_size)
{
    const float* x  = (const float*)d_in[0];
    const float* Wq = (const float*)d_in[1];
    const float* bq = (const float*)d_in[2];
    const float* Wk = (const float*)d_in[3];
    const float* bk = (const float*)d_in[4];
    const float* Wv = (const float*)d_in[5];
    const float* bv = (const float*)d_in[6];
    const float* Wo = (const float*)d_in[7];
    const float* bo = (const float*)d_in[8];
    float* out = (float*)d_out;

    cudaFuncSetAttribute(attn_tc_kernel, cudaFuncAttributeMaxDynamicSharedMemorySize,
                         ATTN_SMEM_BYTES);
    cudaFuncSetAttribute(qkv_tc_kernel, cudaFuncAttributeMaxDynamicSharedMemorySize,
                         GEMM_SMEM_BYTES);
    cudaFuncSetAttribute(proj_tc_kernel, cudaFuncAttributeMaxDynamicSharedMemorySize,
                         GEMM_SMEM_BYTES);

    convert_w_kernel<<<4 * WELEMS / 4 / 256, 256>>>(Wq, Wk, Wv, Wo);
    convert_x_kernel<<<MROWS * DIMD / 4 / 256, 256>>>(x);

    dim3 gqkv(DIMD / 128, MROWS / 128, 3);
    qkv_tc_kernel<<<gqkv, 256, GEMM_SMEM_BYTES>>>(bq, bk, bv);

    attn_tc_kernel<<<(MROWS / 128) * NHEADS, 256, ATTN_SMEM_BYTES>>>();

    dim3 gproj(DIMD / 128, MROWS / 128);
    proj_tc_kernel<<<gproj, 256, GEMM_SMEM_BYTES>>>(bo, out);

    (void)in_sizes; (void)n_in; (void)out_size;
}